// round 7
// baseline (speedup 1.0000x reference)
#include <cuda_runtime.h>
#include <cuda_fp16.h>
#include <math.h>
#include <stdint.h>

#define C_FULL 1024
#define C_HALF 512
#define HW     4096
#define KLOG   2048

// ---------------- scratch (device globals; no runtime allocation) ----------
__device__ __half g_xTm_h[HW*C_FULL], g_xTm_l[HW*C_FULL];
__device__ __half g_xTf_h[HW*C_FULL], g_xTf_l[HW*C_FULL];
__device__ __half g_xTl_h[HW*C_FULL], g_xTl_l[HW*C_FULL];
__device__ __half g_Wq_h [C_HALF*C_FULL], g_Wq_l [C_HALF*C_FULL];
__device__ __half g_Wk1_h[C_HALF*C_FULL], g_Wk1_l[C_HALF*C_FULL];
__device__ __half g_Wk2_h[C_HALF*C_FULL], g_Wk2_l[C_HALF*C_FULL];
__device__ __half g_Wv_h [C_FULL*C_FULL];                 // lo of Wv unused
__device__ __half g_q_h [C_HALF*HW], g_q_l [C_HALF*HW];
__device__ __half g_kf_h[C_HALF*HW], g_kf_l[C_HALF*HW];
__device__ __half g_kl_h[C_HALF*HW], g_kl_l[C_HALF*HW];
__device__ __half g_vT_h[HW*C_FULL];                      // lo of V unused
__device__ float  g_lf0[C_FULL*C_FULL], g_lf1[C_FULL*C_FULL];
__device__ float  g_ll0[C_FULL*C_FULL], g_ll1[C_FULL*C_FULL];
__device__ __half g_S_h[C_FULL*C_FULL], g_S_l[C_FULL*C_FULL];

// ---------------- helpers ---------------------------------------------------
__device__ __forceinline__ uint32_t smem_u32(const void* p) {
    uint32_t r;
    asm("{ .reg .u64 t; cvta.to.shared.u64 t, %1; cvt.u32.u64 %0, t; }"
        : "=r"(r) : "l"(p));
    return r;
}
__device__ __forceinline__ void cp_async16(uint32_t dst, const void* src) {
    asm volatile("cp.async.cg.shared.global [%0], [%1], 16;" :: "r"(dst), "l"(src));
}
__device__ __forceinline__ void cp_commit() { asm volatile("cp.async.commit_group;"); }

__device__ __forceinline__ void ldsm4(uint32_t addr, uint32_t& r0, uint32_t& r1,
                                      uint32_t& r2, uint32_t& r3) {
    asm volatile("ldmatrix.sync.aligned.m8n8.x4.shared.b16 {%0,%1,%2,%3}, [%4];"
                 : "=r"(r0), "=r"(r1), "=r"(r2), "=r"(r3) : "r"(addr));
}
__device__ __forceinline__ void hmma(float* d, const uint32_t* a,
                                     uint32_t b0, uint32_t b1) {
    asm volatile("mma.sync.aligned.m16n8k16.row.col.f32.f16.f16.f32 "
                 "{%0,%1,%2,%3}, {%4,%5,%6,%7}, {%8,%9}, {%0,%1,%2,%3};"
                 : "+f"(d[0]), "+f"(d[1]), "+f"(d[2]), "+f"(d[3])
                 : "r"(a[0]), "r"(a[1]), "r"(a[2]), "r"(a[3]),
                   "r"(b0), "r"(b1));
}

// ---------------- unified multi-job GEMM ------------------------------------
// D = A[M,K'] @ B[N,K']^T over K' = [koff, koff+K), fp16-split, fp32 accum.
// tm bit0: add A_h*B_l; tm bit1: add A_l*B_h (A_h*B_h always).
// mode 0: split-store D+bias[m] -> Ch/Cl        (convs q/kf/kl)
// mode 1: hi-store   D+bias[n] -> Ch            (conv vT)
// mode 2: fp32 store D -> Cf                    (logit partials)
// mode 3: fp32 store gamma*D + 0.5*(xf+xl)->Cf  (final)
struct Jobs {
    const __half* Ah[4]; const __half* Al[4];
    const __half* Bh[4]; const __half* Bl[4];
    __half* Ch[4]; __half* Cl[4]; float* Cf[4];
    const float* bias[4];
    const float* xf; const float* xl; const float* gpt;
    int N[4], K[4], Kld[4], koff[4], gx[4], tm[4], mode[4], blk0[4];
    int njobs;
};

#define BM 128
#define BN 256
#define BK 64
#define NTHR 512
#define TSTRIDE 72                             // 64 halves + 8 pad
#define A_TILE_BYTES (128 * TSTRIDE * 2)       // 18432
#define B_TILE_BYTES (256 * TSTRIDE * 2)       // 36864
#define STAGE_BYTES (2 * A_TILE_BYTES + 2 * B_TILE_BYTES)  // 110592
#define GEMM_SMEM (2 * STAGE_BYTES)            // 221184

__global__ __launch_bounds__(NTHR, 1)
void mma_gemm(Jobs P)
{
    extern __shared__ __half sm[];
    int j = 0;
    #pragma unroll
    for (int t = 1; t < 4; t++)
        if (t < P.njobs && (int)blockIdx.x >= P.blk0[t]) j = t;
    const int rel = blockIdx.x - P.blk0[j];
    const int bx = rel % P.gx[j], by = rel / P.gx[j];

    const __half* __restrict__ Ah = P.Ah[j];
    const __half* __restrict__ Al = P.Al[j];
    const __half* __restrict__ Bh = P.Bh[j];
    const __half* __restrict__ Bl = P.Bl[j];
    const int N = P.N[j], K = P.K[j], Kld = P.Kld[j], koff = P.koff[j];
    const int tm = P.tm[j], mode = P.mode[j];

    const int tid  = threadIdx.x;
    const int lane = tid & 31, wid = tid >> 5;
    const int warp_m = wid & 3, warp_n = wid >> 2;       // 4 x 4 warps, 32x64
    const int bm0 = by * BM, bn0 = bx * BN;
    const uint32_t su = smem_u32(sm);

    float acc[2][8][4];
    #pragma unroll
    for (int i = 0; i < 2; i++)
        #pragma unroll
        for (int q = 0; q < 8; q++)
            #pragma unroll
            for (int k = 0; k < 4; k++) acc[i][q][k] = 0.0f;

#define LOAD_STAGE(s, kt) do {                                                \
    const uint32_t sbase_ = su + (uint32_t)(s) * STAGE_BYTES;                 \
    const size_t col0_ = (size_t)koff + (size_t)(kt) * BK;                    \
    _Pragma("unroll")                                                         \
    for (int it_ = 0; it_ < 2; it_++) {          /* A: 128 rows */            \
        const int c_ = tid + it_ * NTHR;                                      \
        const int row_ = c_ >> 3;                                             \
        const int kc_ = (c_ & 7) * 8;                                         \
        const uint32_t off_ = (uint32_t)(row_ * TSTRIDE + kc_) * 2;           \
        const size_t ga_ = (size_t)(bm0 + row_) * Kld + col0_ + kc_;          \
        cp_async16(sbase_ + off_, Ah + ga_);                                  \
        if (tm & 2) cp_async16(sbase_ + A_TILE_BYTES + off_, Al + ga_);       \
    }                                                                         \
    _Pragma("unroll")                                                         \
    for (int it_ = 0; it_ < 4; it_++) {          /* B: 256 rows */            \
        const int c_ = tid + it_ * NTHR;                                      \
        const int row_ = c_ >> 3;                                             \
        const int kc_ = (c_ & 7) * 8;                                         \
        const uint32_t off_ = (uint32_t)(row_ * TSTRIDE + kc_) * 2;           \
        const size_t gb_ = (size_t)(bn0 + row_) * Kld + col0_ + kc_;          \
        cp_async16(sbase_ + 2 * A_TILE_BYTES + off_, Bh + gb_);               \
        if (tm & 1) cp_async16(sbase_ + 2 * A_TILE_BYTES + B_TILE_BYTES + off_,\
                               Bl + gb_);                                     \
    }                                                                         \
    cp_commit();                                                              \
} while (0)

    const int NT = K / BK;
    LOAD_STAGE(0, 0);

    for (int kt = 0; kt < NT; kt++) {
        if (kt + 1 < NT) {
            LOAD_STAGE((kt + 1) & 1, kt + 1);
            asm volatile("cp.async.wait_group 1;" ::: "memory");
        } else {
            asm volatile("cp.async.wait_group 0;" ::: "memory");
        }
        __syncthreads();

        const uint32_t sbase = su + (uint32_t)(kt & 1) * STAGE_BYTES;
        #pragma unroll
        for (int ks = 0; ks < 4; ks++) {
            uint32_t ah[2][4], al[2][4];
            #pragma unroll
            for (int i = 0; i < 2; i++) {
                const int r   = warp_m * 32 + i * 16 + (lane & 15);
                const int col = ks * 16 + (lane >> 4) * 8;
                const uint32_t ad = sbase + (uint32_t)(r * TSTRIDE + col) * 2;
                ldsm4(ad, ah[i][0], ah[i][1], ah[i][2], ah[i][3]);
                if (tm & 2)
                    ldsm4(ad + A_TILE_BYTES, al[i][0], al[i][1], al[i][2], al[i][3]);
            }
            const int g  = lane >> 3, i8 = lane & 7;
            #pragma unroll
            for (int p = 0; p < 4; p++) {
                const int n   = warp_n * 64 + p * 16 + ((g >> 1) << 3) + i8;
                const int col = ks * 16 + (g & 1) * 8;
                const uint32_t bd = sbase + 2 * A_TILE_BYTES +
                                    (uint32_t)(n * TSTRIDE + col) * 2;
                uint32_t b00, b01, b10, b11;
                ldsm4(bd, b00, b01, b10, b11);
                #pragma unroll
                for (int i = 0; i < 2; i++) {
                    hmma(acc[i][2*p],   ah[i], b00, b01);
                    hmma(acc[i][2*p+1], ah[i], b10, b11);
                }
                if (tm & 2) {
                    #pragma unroll
                    for (int i = 0; i < 2; i++) {
                        hmma(acc[i][2*p],   al[i], b00, b01);
                        hmma(acc[i][2*p+1], al[i], b10, b11);
                    }
                }
                if (tm & 1) {
                    uint32_t c00, c01, c10, c11;
                    ldsm4(bd + B_TILE_BYTES, c00, c01, c10, c11);
                    #pragma unroll
                    for (int i = 0; i < 2; i++) {
                        hmma(acc[i][2*p],   ah[i], c00, c01);
                        hmma(acc[i][2*p+1], ah[i], c10, c11);
                    }
                }
            }
        }
        __syncthreads();
    }
#undef LOAD_STAGE

    // ---- epilogue ----
    const int tq = lane >> 2, tr = lane & 3;
    const float gam = (mode == 3) ? P.gpt[0] : 0.0f;
    #pragma unroll
    for (int i = 0; i < 2; i++) {
        #pragma unroll
        for (int h2 = 0; h2 < 2; h2++) {
            const int row = bm0 + warp_m * 32 + i * 16 + tq + h2 * 8;
            const float bm_ = (mode == 0) ? P.bias[j][row] : 0.0f;
            #pragma unroll
            for (int q = 0; q < 8; q++) {
                const int col = bn0 + warp_n * 64 + q * 8 + tr * 2;
                float v0 = acc[i][q][h2 * 2 + 0];
                float v1 = acc[i][q][h2 * 2 + 1];
                const size_t idx = (size_t)row * N + col;
                if (mode == 0) {
                    v0 += bm_; v1 += bm_;
                    const __half h0 = __float2half_rn(v0);
                    const __half h1 = __float2half_rn(v1);
                    *reinterpret_cast<__half2*>(P.Ch[j] + idx) = __halves2half2(h0, h1);
                    *reinterpret_cast<__half2*>(P.Cl[j] + idx) =
                        __halves2half2(__float2half_rn(v0 - __half2float(h0)),
                                       __float2half_rn(v1 - __half2float(h1)));
                } else if (mode == 1) {
                    v0 += P.bias[j][col]; v1 += P.bias[j][col + 1];
                    *reinterpret_cast<__half2*>(P.Ch[j] + idx) =
                        __halves2half2(__float2half_rn(v0), __float2half_rn(v1));
                } else if (mode == 2) {
                    *reinterpret_cast<float2*>(P.Cf[j] + idx) = make_float2(v0, v1);
                } else {
                    const float2 a2 = *reinterpret_cast<const float2*>(P.xf + idx);
                    const float2 b2 = *reinterpret_cast<const float2*>(P.xl + idx);
                    *reinterpret_cast<float2*>(P.Cf[j] + idx) =
                        make_float2(gam * v0 + 0.5f * (a2.x + b2.x),
                                    gam * v1 + 0.5f * (a2.y + b2.y));
                }
            }
        }
    }
}

// ---------------- batched transpose + fp16 split ----------------------------
struct TJobs { const float* x[3]; __half* th[3]; __half* tl[3]; };
__global__ __launch_bounds__(256)
void transpose_split(TJobs T)
{
    __shared__ float t[32][33];
    const int z = blockIdx.z;
    const float* __restrict__ x = T.x[z];
    __half* __restrict__ th = T.th[z];
    __half* __restrict__ tl = T.tl[z];
    const int tx = threadIdx.x & 31, ty = threadIdx.x >> 5;
    const int c0 = blockIdx.x * 32;
    const int r0 = blockIdx.y * 32;
    #pragma unroll
    for (int i = 0; i < 4; i++)
        t[ty + i * 8][tx] = x[(size_t)(r0 + ty + i * 8) * HW + c0 + tx];
    __syncthreads();
    #pragma unroll
    for (int i = 0; i < 4; i++) {
        const float v = t[tx][ty + i * 8];
        const size_t idx = (size_t)(c0 + ty + i * 8) * C_FULL + r0 + tx;
        const __half h = __float2half_rn(v);
        th[idx] = h;
        tl[idx] = __float2half_rn(v - __half2float(h));
    }
}

// ---------------- merged weight splits (lo optional) ------------------------
struct SJobs { const float* x[4]; __half* h[4]; __half* l[4]; int end[4]; };
__global__ __launch_bounds__(256)
void split4_kernel(SJobs S)
{
    int i = blockIdx.x * 256 + threadIdx.x;
    int j = 0;
    #pragma unroll
    for (int t = 1; t < 4; t++) if (i >= S.end[t - 1]) j = t;
    const int base = (j == 0) ? 0 : S.end[j - 1];
    if (i >= S.end[3]) return;
    const int k = i - base;
    const float v = S.x[j][k];
    const __half hh = __float2half_rn(v);
    S.h[j][k] = hh;
    if (S.l[j]) S.l[j][k] = __float2half_rn(v - __half2float(hh));
}

// ---------------- fused dual softmax over split-K partials ------------------
__global__ __launch_bounds__(256)
void softmax_sum_kernel(const float* __restrict__ LF0, const float* __restrict__ LF1,
                        const float* __restrict__ LL0, const float* __restrict__ LL1,
                        __half* __restrict__ Sh, __half* __restrict__ Sl)
{
    const int row = blockIdx.x;
    const int tid = threadIdx.x;
    __shared__ float red[256];

    const size_t rb = (size_t)row * 1024;
    float vf[4], vl[4];
    #pragma unroll
    for (int k = 0; k < 4; k++) {
        const size_t ix = rb + tid + 256 * k;
        vf[k] = LF0[ix] + LF1[ix];
        vl[k] = LL0[ix] + LL1[ix];
    }

    float m = fmaxf(fmaxf(vf[0], vf[1]), fmaxf(vf[2], vf[3]));
    red[tid] = m; __syncthreads();
    for (int s = 128; s > 0; s >>= 1) { if (tid < s) red[tid] = fmaxf(red[tid], red[tid + s]); __syncthreads(); }
    const float Mf = red[0]; __syncthreads();

    float ef[4], sf = 0.0f;
    #pragma unroll
    for (int k = 0; k < 4; k++) { ef[k] = expf(vf[k] - Mf); sf += ef[k]; }
    red[tid] = sf; __syncthreads();
    for (int s = 128; s > 0; s >>= 1) { if (tid < s) red[tid] += red[tid + s]; __syncthreads(); }
    const float Sf = red[0]; __syncthreads();

    m = fmaxf(fmaxf(vl[0], vl[1]), fmaxf(vl[2], vl[3]));
    red[tid] = m; __syncthreads();
    for (int s = 128; s > 0; s >>= 1) { if (tid < s) red[tid] = fmaxf(red[tid], red[tid + s]); __syncthreads(); }
    const float Ml = red[0]; __syncthreads();

    float el[4], sl = 0.0f;
    #pragma unroll
    for (int k = 0; k < 4; k++) { el[k] = expf(vl[k] - Ml); sl += el[k]; }
    red[tid] = sl; __syncthreads();
    for (int s = 128; s > 0; s >>= 1) { if (tid < s) red[tid] += red[tid + s]; __syncthreads(); }
    const float Sl_ = red[0];

    const float invf = 1.0f / Sf, invl = 1.0f / Sl_;
    #pragma unroll
    for (int k = 0; k < 4; k++) {
        const float v = ef[k] * invf + el[k] * invl;
        const size_t idx = rb + tid + 256 * k;
        const __half h = __float2half_rn(v);
        Sh[idx] = h;
        Sl[idx] = __float2half_rn(v - __half2float(h));
    }
}

// ---------------------------------------------------------------------------
extern "C" void kernel_launch(void* const* d_in, const int* in_sizes, int n_in,
                              void* d_out, int out_size)
{
    (void)in_sizes; (void)n_in; (void)out_size;
    const float* x_f   = (const float*)d_in[0];
    const float* x_m   = (const float*)d_in[1];
    const float* x_l   = (const float*)d_in[2];
    const float* Wq    = (const float*)d_in[3];
    const float* bq    = (const float*)d_in[4];
    const float* Wk1   = (const float*)d_in[5];
    const float* bk1   = (const float*)d_in[6];
    const float* Wk2   = (const float*)d_in[7];
    const float* bk2   = (const float*)d_in[8];
    const float* Wv    = (const float*)d_in[9];
    const float* bv    = (const float*)d_in[10];
    const float* gamma = (const float*)d_in[11];
    float* out = (float*)d_out;

    __half *xTm_h, *xTm_l, *xTf_h, *xTf_l, *xTl_h, *xTl_l;
    __half *wq_h, *wq_l, *wk1_h, *wk1_l, *wk2_h, *wk2_l, *wv_h;
    __half *q_h, *q_l, *kf_h, *kf_l, *kl_h, *kl_l, *vT_h, *s_h, *s_l;
    float *lf0, *lf1, *ll0, *ll1;
    cudaGetSymbolAddress((void**)&xTm_h, g_xTm_h); cudaGetSymbolAddress((void**)&xTm_l, g_xTm_l);
    cudaGetSymbolAddress((void**)&xTf_h, g_xTf_h); cudaGetSymbolAddress((void**)&xTf_l, g_xTf_l);
    cudaGetSymbolAddress((void**)&xTl_h, g_xTl_h); cudaGetSymbolAddress((void**)&xTl_l, g_xTl_l);
    cudaGetSymbolAddress((void**)&wq_h,  g_Wq_h);  cudaGetSymbolAddress((void**)&wq_l,  g_Wq_l);
    cudaGetSymbolAddress((void**)&wk1_h, g_Wk1_h); cudaGetSymbolAddress((void**)&wk1_l, g_Wk1_l);
    cudaGetSymbolAddress((void**)&wk2_h, g_Wk2_h); cudaGetSymbolAddress((void**)&wk2_l, g_Wk2_l);
    cudaGetSymbolAddress((void**)&wv_h,  g_Wv_h);
    cudaGetSymbolAddress((void**)&q_h,  g_q_h);  cudaGetSymbolAddress((void**)&q_l,  g_q_l);
    cudaGetSymbolAddress((void**)&kf_h, g_kf_h); cudaGetSymbolAddress((void**)&kf_l, g_kf_l);
    cudaGetSymbolAddress((void**)&kl_h, g_kl_h); cudaGetSymbolAddress((void**)&kl_l, g_kl_l);
    cudaGetSymbolAddress((void**)&vT_h, g_vT_h);
    cudaGetSymbolAddress((void**)&s_h,  g_S_h);  cudaGetSymbolAddress((void**)&s_l,  g_S_l);
    cudaGetSymbolAddress((void**)&lf0, g_lf0);   cudaGetSymbolAddress((void**)&lf1, g_lf1);
    cudaGetSymbolAddress((void**)&ll0, g_ll0);   cudaGetSymbolAddress((void**)&ll1, g_ll1);

    cudaFuncSetAttribute(mma_gemm, cudaFuncAttributeMaxDynamicSharedMemorySize, GEMM_SMEM);

    // 1) weight splits
    {
        SJobs S = {};
        S.x[0] = Wq;  S.h[0] = wq_h;  S.l[0] = wq_l;
        S.x[1] = Wk1; S.h[1] = wk1_h; S.l[1] = wk1_l;
        S.x[2] = Wk2; S.h[2] = wk2_h; S.l[2] = wk2_l;
        S.x[3] = Wv;  S.h[3] = wv_h;  S.l[3] = nullptr;
        int n0 = C_HALF * C_FULL;
        S.end[0] = n0; S.end[1] = 2 * n0; S.end[2] = 3 * n0;
        S.end[3] = 3 * n0 + C_FULL * C_FULL;
        split4_kernel<<<(S.end[3] + 255) / 256, 256>>>(S);
    }

    // 2) activation transposes + splits
    {
        TJobs T = {};
        T.x[0] = x_m; T.th[0] = xTm_h; T.tl[0] = xTm_l;
        T.x[1] = x_f; T.th[1] = xTf_h; T.tl[1] = xTf_l;
        T.x[2] = x_l; T.th[2] = xTl_h; T.tl[2] = xTl_l;
        transpose_split<<<dim3(HW / 32, C_FULL / 32, 3), 256>>>(T);
    }

    // 3) all 4 conv GEMMs in ONE launch (320 CTAs)
    {
        Jobs P = {};
        const __half* Ahs[3] = {wq_h, wk1_h, wk2_h};
        const __half* Als[3] = {wq_l, wk1_l, wk2_l};
        const __half* Bhs[3] = {xTm_h, xTf_h, xTl_h};
        const __half* Bls[3] = {xTm_l, xTf_l, xTl_l};
        __half* Chs[3] = {q_h, kf_h, kl_h};
        __half* Cls[3] = {q_l, kf_l, kl_l};
        const float* bs[3] = {bq, bk1, bk2};
        for (int t = 0; t < 3; t++) {
            P.Ah[t] = Ahs[t]; P.Al[t] = Als[t]; P.Bh[t] = Bhs[t]; P.Bl[t] = Bls[t];
            P.Ch[t] = Chs[t]; P.Cl[t] = Cls[t]; P.bias[t] = bs[t];
            P.N[t] = HW; P.K[t] = C_FULL; P.Kld[t] = C_FULL; P.koff[t] = 0;
            P.gx[t] = HW / BN;                               // 16
            P.tm[t] = 3; P.mode[t] = 0; P.blk0[t] = t * 64;  // 4 y-tiles * 16
        }
        // job 3: vT = xT_m @ Wv^T + bv[n]  (M=4096, N=1024)
        P.Ah[3] = xTm_h; P.Al[3] = xTm_l; P.Bh[3] = wv_h; P.Bl[3] = nullptr;
        P.Ch[3] = vT_h; P.bias[3] = bv;
        P.N[3] = C_FULL; P.K[3] = C_FULL; P.Kld[3] = C_FULL; P.koff[3] = 0;
        P.gx[3] = C_FULL / BN;                               // 4
        P.tm[3] = 2; P.mode[3] = 1; P.blk0[3] = 192;
        P.njobs = 4;
        mma_gemm<<<320, NTHR, GEMM_SMEM>>>(P);
    }

    // 4) logits, split-K=2 (4 jobs x 32 CTAs = 128)
    {
        Jobs P = {};
        const __half* As[4] = {kf_h, kf_h, kl_h, kl_h};
        const __half* Als[4] = {kf_l, kf_l, kl_l, kl_l};
        float* Cs[4] = {lf0, lf1, ll0, ll1};
        const int kos[4] = {0, 1024, 0, 1024};
        for (int t = 0; t < 4; t++) {
            P.Ah[t] = As[t]; P.Al[t] = Als[t]; P.Bh[t] = q_h; P.Bl[t] = q_l;
            P.Cf[t] = Cs[t];
            P.N[t] = C_FULL; P.K[t] = 1024; P.Kld[t] = KLOG; P.koff[t] = kos[t];
            P.gx[t] = C_FULL / BN;                           // 4
            P.tm[t] = 3; P.mode[t] = 2; P.blk0[t] = t * 32;  // 8 y-tiles * 4
        }
        P.njobs = 4;
        mma_gemm<<<128, NTHR, GEMM_SMEM>>>(P);
    }

    // 5) S = softmax(lf0+lf1) + softmax(ll0+ll1)
    softmax_sum_kernel<<<C_FULL, 256>>>(lf0, lf1, ll0, ll1, s_h, s_l);

    // 6) out = gamma * (S @ vT^T) + 0.5*(x_f + x_l)   (128 CTAs)
    {
        Jobs P = {};
        P.Ah[0] = s_h; P.Al[0] = s_l; P.Bh[0] = vT_h; P.Bl[0] = nullptr;
        P.Cf[0] = out; P.xf = x_f; P.xl = x_l; P.gpt = gamma;
        P.N[0] = HW; P.K[0] = C_FULL; P.Kld[0] = C_FULL; P.koff[0] = 0;
        P.gx[0] = HW / BN;                                   // 16
        P.tm[0] = 2; P.mode[0] = 3; P.blk0[0] = 0;
        P.njobs = 1;
        mma_gemm<<<128, NTHR, GEMM_SMEM>>>(P);
    }
}

// round 8
// speedup vs baseline: 1.0042x; 1.0042x over previous
#include <cuda_runtime.h>
#include <cuda_fp16.h>
#include <math.h>
#include <stdint.h>

#define C_FULL 1024
#define C_HALF 512
#define HW     4096
#define KLOG   2048

// ---------------- scratch (device globals; no runtime allocation) ----------
__device__ __half g_xTm_h[HW*C_FULL], g_xTm_l[HW*C_FULL];
__device__ __half g_xTf_h[HW*C_FULL], g_xTf_l[HW*C_FULL];
__device__ __half g_xTl_h[HW*C_FULL], g_xTl_l[HW*C_FULL];
__device__ __half g_Wq_h [C_HALF*C_FULL], g_Wq_l [C_HALF*C_FULL];
__device__ __half g_Wk1_h[C_HALF*C_FULL], g_Wk1_l[C_HALF*C_FULL];
__device__ __half g_Wk2_h[C_HALF*C_FULL], g_Wk2_l[C_HALF*C_FULL];
__device__ __half g_Wv_h [C_FULL*C_FULL];                 // lo of Wv unused
__device__ __half g_q_h [C_HALF*HW], g_q_l [C_HALF*HW];
__device__ __half g_kf_h[C_HALF*HW], g_kf_l[C_HALF*HW];
__device__ __half g_kl_h[C_HALF*HW], g_kl_l[C_HALF*HW];
__device__ __half g_vT_h[HW*C_FULL];                      // lo of V unused
__device__ float  g_lf0[C_FULL*C_FULL], g_lf1[C_FULL*C_FULL];
__device__ float  g_ll0[C_FULL*C_FULL], g_ll1[C_FULL*C_FULL];
__device__ __half g_S_h[C_FULL*C_FULL], g_S_l[C_FULL*C_FULL];

// ---------------- helpers ---------------------------------------------------
__device__ __forceinline__ uint32_t smem_u32(const void* p) {
    uint32_t r;
    asm("{ .reg .u64 t; cvta.to.shared.u64 t, %1; cvt.u32.u64 %0, t; }"
        : "=r"(r) : "l"(p));
    return r;
}
__device__ __forceinline__ void cp_async16(uint32_t dst, const void* src) {
    asm volatile("cp.async.cg.shared.global [%0], [%1], 16;" :: "r"(dst), "l"(src));
}
__device__ __forceinline__ void cp_commit() { asm volatile("cp.async.commit_group;"); }

__device__ __forceinline__ void ldsm4(uint32_t addr, uint32_t& r0, uint32_t& r1,
                                      uint32_t& r2, uint32_t& r3) {
    asm volatile("ldmatrix.sync.aligned.m8n8.x4.shared.b16 {%0,%1,%2,%3}, [%4];"
                 : "=r"(r0), "=r"(r1), "=r"(r2), "=r"(r3) : "r"(addr));
}
__device__ __forceinline__ void hmma(float* d, const uint32_t* a,
                                     uint32_t b0, uint32_t b1) {
    asm volatile("mma.sync.aligned.m16n8k16.row.col.f32.f16.f16.f32 "
                 "{%0,%1,%2,%3}, {%4,%5,%6,%7}, {%8,%9}, {%0,%1,%2,%3};"
                 : "+f"(d[0]), "+f"(d[1]), "+f"(d[2]), "+f"(d[3])
                 : "r"(a[0]), "r"(a[1]), "r"(a[2]), "r"(a[3]),
                   "r"(b0), "r"(b1));
}

// ---------------- unified multi-job GEMM ------------------------------------
// D = A[M,K'] @ B[N,K']^T over K' = [koff, koff+K), fp16-split, fp32 accum.
// tm bit0: add A_h*B_l; tm bit1: add A_l*B_h (A_h*B_h always).
// mode 0: split-store D+bias[m] -> Ch/Cl        (convs q/kf/kl)
// mode 1: hi-store   D+bias[n] -> Ch            (conv vT)
// mode 2: fp32 store D -> Cf                    (logit partials)
// mode 3: fp32 store gamma*D + 0.5*(xf+xl)->Cf  (final)
struct Jobs {
    const __half* Ah[4]; const __half* Al[4];
    const __half* Bh[4]; const __half* Bl[4];
    __half* Ch[4]; __half* Cl[4]; float* Cf[4];
    const float* bias[4];
    const float* xf; const float* xl; const float* gpt;
    int N[4], K[4], Kld[4], koff[4], gx[4], tm[4], mode[4], blk0[4];
    int njobs;
};

#define BM 128
#define BN 256
#define BK 64
#define NTHR 512
#define TSTRIDE 72                             // 64 halves + 8 pad
#define A_TILE_BYTES (128 * TSTRIDE * 2)       // 18432
#define B_TILE_BYTES (256 * TSTRIDE * 2)       // 36864
#define STAGE_BYTES (2 * A_TILE_BYTES + 2 * B_TILE_BYTES)  // 110592
#define GEMM_SMEM (2 * STAGE_BYTES)            // 221184

__global__ __launch_bounds__(NTHR, 1)
void mma_gemm(Jobs P)
{
    extern __shared__ __half sm[];
    int j = 0;
    #pragma unroll
    for (int t = 1; t < 4; t++)
        if (t < P.njobs && (int)blockIdx.x >= P.blk0[t]) j = t;
    const int rel = blockIdx.x - P.blk0[j];
    const int bx = rel % P.gx[j], by = rel / P.gx[j];

    const __half* __restrict__ Ah = P.Ah[j];
    const __half* __restrict__ Al = P.Al[j];
    const __half* __restrict__ Bh = P.Bh[j];
    const __half* __restrict__ Bl = P.Bl[j];
    const int N = P.N[j], K = P.K[j], Kld = P.Kld[j], koff = P.koff[j];
    const int tm = P.tm[j], mode = P.mode[j];

    const int tid  = threadIdx.x;
    const int lane = tid & 31, wid = tid >> 5;
    const int warp_m = wid & 3, warp_n = wid >> 2;       // 4 x 4 warps, 32x64
    const int bm0 = by * BM, bn0 = bx * BN;
    const uint32_t su = smem_u32(sm);

    float acc[2][8][4];
    #pragma unroll
    for (int i = 0; i < 2; i++)
        #pragma unroll
        for (int q = 0; q < 8; q++)
            #pragma unroll
            for (int k = 0; k < 4; k++) acc[i][q][k] = 0.0f;

#define LOAD_STAGE(s, kt) do {                                                \
    const uint32_t sbase_ = su + (uint32_t)(s) * STAGE_BYTES;                 \
    const size_t col0_ = (size_t)koff + (size_t)(kt) * BK;                    \
    _Pragma("unroll")                                                         \
    for (int it_ = 0; it_ < 2; it_++) {          /* A: 128 rows */            \
        const int c_ = tid + it_ * NTHR;                                      \
        const int row_ = c_ >> 3;                                             \
        const int kc_ = (c_ & 7) * 8;                                         \
        const uint32_t off_ = (uint32_t)(row_ * TSTRIDE + kc_) * 2;           \
        const size_t ga_ = (size_t)(bm0 + row_) * Kld + col0_ + kc_;          \
        cp_async16(sbase_ + off_, Ah + ga_);                                  \
        if (tm & 2) cp_async16(sbase_ + A_TILE_BYTES + off_, Al + ga_);       \
    }                                                                         \
    _Pragma("unroll")                                                         \
    for (int it_ = 0; it_ < 4; it_++) {          /* B: 256 rows */            \
        const int c_ = tid + it_ * NTHR;                                      \
        const int row_ = c_ >> 3;                                             \
        const int kc_ = (c_ & 7) * 8;                                         \
        const uint32_t off_ = (uint32_t)(row_ * TSTRIDE + kc_) * 2;           \
        const size_t gb_ = (size_t)(bn0 + row_) * Kld + col0_ + kc_;          \
        cp_async16(sbase_ + 2 * A_TILE_BYTES + off_, Bh + gb_);               \
        if (tm & 1) cp_async16(sbase_ + 2 * A_TILE_BYTES + B_TILE_BYTES + off_,\
                               Bl + gb_);                                     \
    }                                                                         \
    cp_commit();                                                              \
} while (0)

    const int NT = K / BK;
    LOAD_STAGE(0, 0);

    for (int kt = 0; kt < NT; kt++) {
        if (kt + 1 < NT) {
            LOAD_STAGE((kt + 1) & 1, kt + 1);
            asm volatile("cp.async.wait_group 1;" ::: "memory");
        } else {
            asm volatile("cp.async.wait_group 0;" ::: "memory");
        }
        __syncthreads();

        const uint32_t sbase = su + (uint32_t)(kt & 1) * STAGE_BYTES;
        #pragma unroll
        for (int ks = 0; ks < 4; ks++) {
            uint32_t ah[2][4], al[2][4];
            #pragma unroll
            for (int i = 0; i < 2; i++) {
                const int r   = warp_m * 32 + i * 16 + (lane & 15);
                const int col = ks * 16 + (lane >> 4) * 8;
                const uint32_t ad = sbase + (uint32_t)(r * TSTRIDE + col) * 2;
                ldsm4(ad, ah[i][0], ah[i][1], ah[i][2], ah[i][3]);
                if (tm & 2)
                    ldsm4(ad + A_TILE_BYTES, al[i][0], al[i][1], al[i][2], al[i][3]);
            }
            const int g  = lane >> 3, i8 = lane & 7;
            const int n0r = warp_n * 64 + ((g >> 1) << 3) + i8;
            const int bcol = ks * 16 + (g & 1) * 8;
            const uint32_t bd0 = sbase + 2 * A_TILE_BYTES +
                                 (uint32_t)(n0r * TSTRIDE + bcol) * 2;
            // software pipeline: B-hi double-buffered over p
            uint32_t bh0, bh1, bh2, bh3;      // current
            uint32_t bn0r_, bn1_, bn2_, bn3_; // next
            ldsm4(bd0, bh0, bh1, bh2, bh3);
            #pragma unroll
            for (int p = 0; p < 4; p++) {
                const uint32_t bd = bd0 + (uint32_t)(p * 16 * TSTRIDE * 2);
                if (p < 3)
                    ldsm4(bd + (uint32_t)(16 * TSTRIDE * 2), bn0r_, bn1_, bn2_, bn3_);
                uint32_t c0, c1, c2, c3;
                if (tm & 1)
                    ldsm4(bd + B_TILE_BYTES, c0, c1, c2, c3);
                #pragma unroll
                for (int i = 0; i < 2; i++) {
                    hmma(acc[i][2*p],   ah[i], bh0, bh1);
                    hmma(acc[i][2*p+1], ah[i], bh2, bh3);
                }
                if (tm & 2) {
                    #pragma unroll
                    for (int i = 0; i < 2; i++) {
                        hmma(acc[i][2*p],   al[i], bh0, bh1);
                        hmma(acc[i][2*p+1], al[i], bh2, bh3);
                    }
                }
                if (tm & 1) {
                    #pragma unroll
                    for (int i = 0; i < 2; i++) {
                        hmma(acc[i][2*p],   ah[i], c0, c1);
                        hmma(acc[i][2*p+1], ah[i], c2, c3);
                    }
                }
                bh0 = bn0r_; bh1 = bn1_; bh2 = bn2_; bh3 = bn3_;
            }
        }
        __syncthreads();
    }
#undef LOAD_STAGE

    // ---- epilogue ----
    const int tq = lane >> 2, tr = lane & 3;
    const float gam = (mode == 3) ? P.gpt[0] : 0.0f;
    #pragma unroll
    for (int i = 0; i < 2; i++) {
        #pragma unroll
        for (int h2 = 0; h2 < 2; h2++) {
            const int row = bm0 + warp_m * 32 + i * 16 + tq + h2 * 8;
            const float bm_ = (mode == 0) ? P.bias[j][row] : 0.0f;
            #pragma unroll
            for (int q = 0; q < 8; q++) {
                const int col = bn0 + warp_n * 64 + q * 8 + tr * 2;
                float v0 = acc[i][q][h2 * 2 + 0];
                float v1 = acc[i][q][h2 * 2 + 1];
                const size_t idx = (size_t)row * N + col;
                if (mode == 0) {
                    v0 += bm_; v1 += bm_;
                    const __half h0 = __float2half_rn(v0);
                    const __half h1 = __float2half_rn(v1);
                    *reinterpret_cast<__half2*>(P.Ch[j] + idx) = __halves2half2(h0, h1);
                    *reinterpret_cast<__half2*>(P.Cl[j] + idx) =
                        __halves2half2(__float2half_rn(v0 - __half2float(h0)),
                                       __float2half_rn(v1 - __half2float(h1)));
                } else if (mode == 1) {
                    v0 += P.bias[j][col]; v1 += P.bias[j][col + 1];
                    *reinterpret_cast<__half2*>(P.Ch[j] + idx) =
                        __halves2half2(__float2half_rn(v0), __float2half_rn(v1));
                } else if (mode == 2) {
                    *reinterpret_cast<float2*>(P.Cf[j] + idx) = make_float2(v0, v1);
                } else {
                    const float2 a2 = *reinterpret_cast<const float2*>(P.xf + idx);
                    const float2 b2 = *reinterpret_cast<const float2*>(P.xl + idx);
                    *reinterpret_cast<float2*>(P.Cf[j] + idx) =
                        make_float2(gam * v0 + 0.5f * (a2.x + b2.x),
                                    gam * v1 + 0.5f * (a2.y + b2.y));
                }
            }
        }
    }
}

// ---------------- batched transpose + fp16 split ----------------------------
struct TJobs { const float* x[3]; __half* th[3]; __half* tl[3]; };
__global__ __launch_bounds__(256)
void transpose_split(TJobs T)
{
    __shared__ float t[32][33];
    const int z = blockIdx.z;
    const float* __restrict__ x = T.x[z];
    __half* __restrict__ th = T.th[z];
    __half* __restrict__ tl = T.tl[z];
    const int tx = threadIdx.x & 31, ty = threadIdx.x >> 5;
    const int c0 = blockIdx.x * 32;
    const int r0 = blockIdx.y * 32;
    #pragma unroll
    for (int i = 0; i < 4; i++)
        t[ty + i * 8][tx] = x[(size_t)(r0 + ty + i * 8) * HW + c0 + tx];
    __syncthreads();
    #pragma unroll
    for (int i = 0; i < 4; i++) {
        const float v = t[tx][ty + i * 8];
        const size_t idx = (size_t)(c0 + ty + i * 8) * C_FULL + r0 + tx;
        const __half h = __float2half_rn(v);
        th[idx] = h;
        tl[idx] = __float2half_rn(v - __half2float(h));
    }
}

// ---------------- merged weight splits (lo optional) ------------------------
struct SJobs { const float* x[4]; __half* h[4]; __half* l[4]; int end[4]; };
__global__ __launch_bounds__(256)
void split4_kernel(SJobs S)
{
    int i = blockIdx.x * 256 + threadIdx.x;
    int j = 0;
    #pragma unroll
    for (int t = 1; t < 4; t++) if (i >= S.end[t - 1]) j = t;
    const int base = (j == 0) ? 0 : S.end[j - 1];
    if (i >= S.end[3]) return;
    const int k = i - base;
    const float v = S.x[j][k];
    const __half hh = __float2half_rn(v);
    S.h[j][k] = hh;
    if (S.l[j]) S.l[j][k] = __float2half_rn(v - __half2float(hh));
}

// ---------------- fused dual softmax over split-K partials ------------------
__global__ __launch_bounds__(256)
void softmax_sum_kernel(const float* __restrict__ LF0, const float* __restrict__ LF1,
                        const float* __restrict__ LL0, const float* __restrict__ LL1,
                        __half* __restrict__ Sh, __half* __restrict__ Sl)
{
    const int row = blockIdx.x;
    const int tid = threadIdx.x;
    __shared__ float red[256];

    const size_t rb = (size_t)row * 1024;
    float vf[4], vl[4];
    #pragma unroll
    for (int k = 0; k < 4; k++) {
        const size_t ix = rb + tid + 256 * k;
        vf[k] = LF0[ix] + LF1[ix];
        vl[k] = LL0[ix] + LL1[ix];
    }

    float m = fmaxf(fmaxf(vf[0], vf[1]), fmaxf(vf[2], vf[3]));
    red[tid] = m; __syncthreads();
    for (int s = 128; s > 0; s >>= 1) { if (tid < s) red[tid] = fmaxf(red[tid], red[tid + s]); __syncthreads(); }
    const float Mf = red[0]; __syncthreads();

    float ef[4], sf = 0.0f;
    #pragma unroll
    for (int k = 0; k < 4; k++) { ef[k] = expf(vf[k] - Mf); sf += ef[k]; }
    red[tid] = sf; __syncthreads();
    for (int s = 128; s > 0; s >>= 1) { if (tid < s) red[tid] += red[tid + s]; __syncthreads(); }
    const float Sf = red[0]; __syncthreads();

    m = fmaxf(fmaxf(vl[0], vl[1]), fmaxf(vl[2], vl[3]));
    red[tid] = m; __syncthreads();
    for (int s = 128; s > 0; s >>= 1) { if (tid < s) red[tid] = fmaxf(red[tid], red[tid + s]); __syncthreads(); }
    const float Ml = red[0]; __syncthreads();

    float el[4], sl = 0.0f;
    #pragma unroll
    for (int k = 0; k < 4; k++) { el[k] = expf(vl[k] - Ml); sl += el[k]; }
    red[tid] = sl; __syncthreads();
    for (int s = 128; s > 0; s >>= 1) { if (tid < s) red[tid] += red[tid + s]; __syncthreads(); }
    const float Sl_ = red[0];

    const float invf = 1.0f / Sf, invl = 1.0f / Sl_;
    #pragma unroll
    for (int k = 0; k < 4; k++) {
        const float v = ef[k] * invf + el[k] * invl;
        const size_t idx = rb + tid + 256 * k;
        const __half h = __float2half_rn(v);
        Sh[idx] = h;
        Sl[idx] = __float2half_rn(v - __half2float(h));
    }
}

// ---------------------------------------------------------------------------
extern "C" void kernel_launch(void* const* d_in, const int* in_sizes, int n_in,
                              void* d_out, int out_size)
{
    (void)in_sizes; (void)n_in; (void)out_size;
    const float* x_f   = (const float*)d_in[0];
    const float* x_m   = (const float*)d_in[1];
    const float* x_l   = (const float*)d_in[2];
    const float* Wq    = (const float*)d_in[3];
    const float* bq    = (const float*)d_in[4];
    const float* Wk1   = (const float*)d_in[5];
    const float* bk1   = (const float*)d_in[6];
    const float* Wk2   = (const float*)d_in[7];
    const float* bk2   = (const float*)d_in[8];
    const float* Wv    = (const float*)d_in[9];
    const float* bv    = (const float*)d_in[10];
    const float* gamma = (const float*)d_in[11];
    float* out = (float*)d_out;

    __half *xTm_h, *xTm_l, *xTf_h, *xTf_l, *xTl_h, *xTl_l;
    __half *wq_h, *wq_l, *wk1_h, *wk1_l, *wk2_h, *wk2_l, *wv_h;
    __half *q_h, *q_l, *kf_h, *kf_l, *kl_h, *kl_l, *vT_h, *s_h, *s_l;
    float *lf0, *lf1, *ll0, *ll1;
    cudaGetSymbolAddress((void**)&xTm_h, g_xTm_h); cudaGetSymbolAddress((void**)&xTm_l, g_xTm_l);
    cudaGetSymbolAddress((void**)&xTf_h, g_xTf_h); cudaGetSymbolAddress((void**)&xTf_l, g_xTf_l);
    cudaGetSymbolAddress((void**)&xTl_h, g_xTl_h); cudaGetSymbolAddress((void**)&xTl_l, g_xTl_l);
    cudaGetSymbolAddress((void**)&wq_h,  g_Wq_h);  cudaGetSymbolAddress((void**)&wq_l,  g_Wq_l);
    cudaGetSymbolAddress((void**)&wk1_h, g_Wk1_h); cudaGetSymbolAddress((void**)&wk1_l, g_Wk1_l);
    cudaGetSymbolAddress((void**)&wk2_h, g_Wk2_h); cudaGetSymbolAddress((void**)&wk2_l, g_Wk2_l);
    cudaGetSymbolAddress((void**)&wv_h,  g_Wv_h);
    cudaGetSymbolAddress((void**)&q_h,  g_q_h);  cudaGetSymbolAddress((void**)&q_l,  g_q_l);
    cudaGetSymbolAddress((void**)&kf_h, g_kf_h); cudaGetSymbolAddress((void**)&kf_l, g_kf_l);
    cudaGetSymbolAddress((void**)&kl_h, g_kl_h); cudaGetSymbolAddress((void**)&kl_l, g_kl_l);
    cudaGetSymbolAddress((void**)&vT_h, g_vT_h);
    cudaGetSymbolAddress((void**)&s_h,  g_S_h);  cudaGetSymbolAddress((void**)&s_l,  g_S_l);
    cudaGetSymbolAddress((void**)&lf0, g_lf0);   cudaGetSymbolAddress((void**)&lf1, g_lf1);
    cudaGetSymbolAddress((void**)&ll0, g_ll0);   cudaGetSymbolAddress((void**)&ll1, g_ll1);

    cudaFuncSetAttribute(mma_gemm, cudaFuncAttributeMaxDynamicSharedMemorySize, GEMM_SMEM);

    // 1) weight splits
    {
        SJobs S = {};
        S.x[0] = Wq;  S.h[0] = wq_h;  S.l[0] = wq_l;
        S.x[1] = Wk1; S.h[1] = wk1_h; S.l[1] = wk1_l;
        S.x[2] = Wk2; S.h[2] = wk2_h; S.l[2] = wk2_l;
        S.x[3] = Wv;  S.h[3] = wv_h;  S.l[3] = nullptr;
        int n0 = C_HALF * C_FULL;
        S.end[0] = n0; S.end[1] = 2 * n0; S.end[2] = 3 * n0;
        S.end[3] = 3 * n0 + C_FULL * C_FULL;
        split4_kernel<<<(S.end[3] + 255) / 256, 256>>>(S);
    }

    // 2) activation transposes + splits
    {
        TJobs T = {};
        T.x[0] = x_m; T.th[0] = xTm_h; T.tl[0] = xTm_l;
        T.x[1] = x_f; T.th[1] = xTf_h; T.tl[1] = xTf_l;
        T.x[2] = x_l; T.th[2] = xTl_h; T.tl[2] = xTl_l;
        transpose_split<<<dim3(HW / 32, C_FULL / 32, 3), 256>>>(T);
    }

    // 3) all 4 conv GEMMs in ONE launch (320 CTAs)
    {
        Jobs P = {};
        const __half* Ahs[3] = {wq_h, wk1_h, wk2_h};
        const __half* Als[3] = {wq_l, wk1_l, wk2_l};
        const __half* Bhs[3] = {xTm_h, xTf_h, xTl_h};
        const __half* Bls[3] = {xTm_l, xTf_l, xTl_l};
        __half* Chs[3] = {q_h, kf_h, kl_h};
        __half* Cls[3] = {q_l, kf_l, kl_l};
        const float* bs[3] = {bq, bk1, bk2};
        for (int t = 0; t < 3; t++) {
            P.Ah[t] = Ahs[t]; P.Al[t] = Als[t]; P.Bh[t] = Bhs[t]; P.Bl[t] = Bls[t];
            P.Ch[t] = Chs[t]; P.Cl[t] = Cls[t]; P.bias[t] = bs[t];
            P.N[t] = HW; P.K[t] = C_FULL; P.Kld[t] = C_FULL; P.koff[t] = 0;
            P.gx[t] = HW / BN;                               // 16
            P.tm[t] = 3; P.mode[t] = 0; P.blk0[t] = t * 64;
        }
        P.Ah[3] = xTm_h; P.Al[3] = xTm_l; P.Bh[3] = wv_h; P.Bl[3] = nullptr;
        P.Ch[3] = vT_h; P.bias[3] = bv;
        P.N[3] = C_FULL; P.K[3] = C_FULL; P.Kld[3] = C_FULL; P.koff[3] = 0;
        P.gx[3] = C_FULL / BN;                               // 4
        P.tm[3] = 2; P.mode[3] = 1; P.blk0[3] = 192;
        P.njobs = 4;
        mma_gemm<<<320, NTHR, GEMM_SMEM>>>(P);
    }

    // 4) logits, split-K=2 (4 jobs x 32 CTAs = 128)
    {
        Jobs P = {};
        const __half* As[4] = {kf_h, kf_h, kl_h, kl_h};
        const __half* Als[4] = {kf_l, kf_l, kl_l, kl_l};
        float* Cs[4] = {lf0, lf1, ll0, ll1};
        const int kos[4] = {0, 1024, 0, 1024};
        for (int t = 0; t < 4; t++) {
            P.Ah[t] = As[t]; P.Al[t] = Als[t]; P.Bh[t] = q_h; P.Bl[t] = q_l;
            P.Cf[t] = Cs[t];
            P.N[t] = C_FULL; P.K[t] = 1024; P.Kld[t] = KLOG; P.koff[t] = kos[t];
            P.gx[t] = C_FULL / BN;                           // 4
            P.tm[t] = 3; P.mode[t] = 2; P.blk0[t] = t * 32;
        }
        P.njobs = 4;
        mma_gemm<<<128, NTHR, GEMM_SMEM>>>(P);
    }

    // 5) S = softmax(lf0+lf1) + softmax(ll0+ll1)
    softmax_sum_kernel<<<C_FULL, 256>>>(lf0, lf1, ll0, ll1, s_h, s_l);

    // 6) out = gamma * (S @ vT^T) + 0.5*(x_f + x_l)   (128 CTAs)
    {
        Jobs P = {};
        P.Ah[0] = s_h; P.Al[0] = s_l; P.Bh[0] = vT_h; P.Bl[0] = nullptr;
        P.Cf[0] = out; P.xf = x_f; P.xl = x_l; P.gpt = gamma;
        P.N[0] = HW; P.K[0] = C_FULL; P.Kld[0] = C_FULL; P.koff[0] = 0;
        P.gx[0] = HW / BN;                                   // 16
        P.tm[0] = 2; P.mode[0] = 3; P.blk0[0] = 0;
        P.njobs = 1;
        mma_gemm<<<128, NTHR, GEMM_SMEM>>>(P);
    }
}

// round 9
// speedup vs baseline: 1.0540x; 1.0495x over previous
#include <cuda_runtime.h>
#include <cuda_fp16.h>
#include <math.h>
#include <stdint.h>

#define C_FULL 1024
#define C_HALF 512
#define HW     4096
#define KLOG   2048

// ---------------- scratch (device globals; no runtime allocation) ----------
__device__ __half g_xTm_h[HW*C_FULL], g_xTm_l[HW*C_FULL];
__device__ __half g_xTf_h[HW*C_FULL], g_xTf_l[HW*C_FULL];
__device__ __half g_xTl_h[HW*C_FULL], g_xTl_l[HW*C_FULL];
__device__ __half g_Wq_h [C_HALF*C_FULL], g_Wq_l [C_HALF*C_FULL];
__device__ __half g_Wk1_h[C_HALF*C_FULL], g_Wk1_l[C_HALF*C_FULL];
__device__ __half g_Wk2_h[C_HALF*C_FULL], g_Wk2_l[C_HALF*C_FULL];
__device__ __half g_Wv_h [C_FULL*C_FULL];                 // lo of Wv unused
__device__ __half g_q_h [C_HALF*HW], g_q_l [C_HALF*HW];
__device__ __half g_kf_h[C_HALF*HW], g_kf_l[C_HALF*HW];
__device__ __half g_kl_h[C_HALF*HW], g_kl_l[C_HALF*HW];
__device__ __half g_vT_h[HW*C_FULL];                      // lo of V unused
__device__ float  g_lf0[C_FULL*C_FULL], g_lf1[C_FULL*C_FULL];
__device__ float  g_ll0[C_FULL*C_FULL], g_ll1[C_FULL*C_FULL];
__device__ __half g_S_h[C_FULL*C_FULL], g_S_l[C_FULL*C_FULL];

// ---------------- helpers ---------------------------------------------------
__device__ __forceinline__ uint32_t smem_u32(const void* p) {
    uint32_t r;
    asm("{ .reg .u64 t; cvta.to.shared.u64 t, %1; cvt.u32.u64 %0, t; }"
        : "=r"(r) : "l"(p));
    return r;
}
__device__ __forceinline__ void cp_async16(uint32_t dst, const void* src) {
    asm volatile("cp.async.cg.shared.global [%0], [%1], 16;" :: "r"(dst), "l"(src));
}
__device__ __forceinline__ void cp_commit() { asm volatile("cp.async.commit_group;"); }

__device__ __forceinline__ void ldsm4(uint32_t addr, uint32_t& r0, uint32_t& r1,
                                      uint32_t& r2, uint32_t& r3) {
    asm volatile("ldmatrix.sync.aligned.m8n8.x4.shared.b16 {%0,%1,%2,%3}, [%4];"
                 : "=r"(r0), "=r"(r1), "=r"(r2), "=r"(r3) : "r"(addr));
}
__device__ __forceinline__ void hmma(float* d, const uint32_t* a,
                                     uint32_t b0, uint32_t b1) {
    asm volatile("mma.sync.aligned.m16n8k16.row.col.f32.f16.f16.f32 "
                 "{%0,%1,%2,%3}, {%4,%5,%6,%7}, {%8,%9}, {%0,%1,%2,%3};"
                 : "+f"(d[0]), "+f"(d[1]), "+f"(d[2]), "+f"(d[3])
                 : "r"(a[0]), "r"(a[1]), "r"(a[2]), "r"(a[3]),
                   "r"(b0), "r"(b1));
}

// ---------------- unified multi-job GEMM ------------------------------------
// D = A[M,K'] @ B[N,K']^T over K' = [koff, koff+K), fp16-split, fp32 accum.
// tm bit0: add A_h*B_l; tm bit1: add A_l*B_h (A_h*B_h always).
// mode 0: split-store D+bias[m] -> Ch/Cl        (convs q/kf/kl)
// mode 1: hi-store   D+bias[n] -> Ch            (conv vT)
// mode 2: fp32 store D -> Cf                    (logit partials)
// mode 3: fp32 store gamma*D + 0.5*(xf+xl)->Cf  (final)
struct Jobs {
    const __half* Ah[4]; const __half* Al[4];
    const __half* Bh[4]; const __half* Bl[4];
    __half* Ch[4]; __half* Cl[4]; float* Cf[4];
    const float* bias[4];
    const float* xf; const float* xl; const float* gpt;
    int N[4], K[4], Kld[4], koff[4], gx[4], tm[4], mode[4], blk0[4];
    int njobs;
};

#define BM 128
#define BN 128
#define BK 32
#define NTHR 256
#define TSTRIDE 40                             // 32 halves + 8 pad
#define TILE_BYTES (128 * TSTRIDE * 2)         // 10240
#define STAGE_BYTES (4 * TILE_BYTES)           // 40960 (Ah, Al, Bh, Bl)
#define GEMM_SMEM (2 * STAGE_BYTES)            // 81920  -> 2 CTAs/SM

__global__ __launch_bounds__(NTHR, 2)
void mma_gemm(Jobs P)
{
    extern __shared__ __half sm[];
    int j = 0;
    #pragma unroll
    for (int t = 1; t < 4; t++)
        if (t < P.njobs && (int)blockIdx.x >= P.blk0[t]) j = t;
    const int rel = blockIdx.x - P.blk0[j];
    const int bx = rel % P.gx[j], by = rel / P.gx[j];

    const __half* __restrict__ Ah = P.Ah[j];
    const __half* __restrict__ Al = P.Al[j];
    const __half* __restrict__ Bh = P.Bh[j];
    const __half* __restrict__ Bl = P.Bl[j];
    const int N = P.N[j], K = P.K[j], Kld = P.Kld[j], koff = P.koff[j];
    const int tm = P.tm[j], mode = P.mode[j];

    const int tid  = threadIdx.x;
    const int lane = tid & 31, wid = tid >> 5;
    const int warp_m = wid & 3, warp_n = wid >> 2;       // 4 x 2 warps, 32x64
    const int bm0 = by * BM, bn0 = bx * BN;
    const uint32_t su = smem_u32(sm);

    float acc[2][8][4];
    #pragma unroll
    for (int i = 0; i < 2; i++)
        #pragma unroll
        for (int q = 0; q < 8; q++)
            #pragma unroll
            for (int k = 0; k < 4; k++) acc[i][q][k] = 0.0f;

#define LOAD_STAGE(s, kt) do {                                                \
    const uint32_t sbase_ = su + (uint32_t)(s) * STAGE_BYTES;                 \
    const size_t col0_ = (size_t)koff + (size_t)(kt) * BK;                    \
    _Pragma("unroll")                                                         \
    for (int it_ = 0; it_ < 2; it_++) {                                       \
        const int c_ = tid + it_ * NTHR;       /* 0..511 */                   \
        const int row_ = c_ >> 2;              /* 0..127 */                   \
        const int kc_ = (c_ & 3) * 8;          /* 0,8,16,24 */                \
        const uint32_t off_ = (uint32_t)(row_ * TSTRIDE + kc_) * 2;           \
        const size_t ga_ = (size_t)(bm0 + row_) * Kld + col0_ + kc_;          \
        const size_t gb_ = (size_t)(bn0 + row_) * Kld + col0_ + kc_;          \
        cp_async16(sbase_ + 0 * TILE_BYTES + off_, Ah + ga_);                 \
        cp_async16(sbase_ + 2 * TILE_BYTES + off_, Bh + gb_);                 \
        if (tm & 2) cp_async16(sbase_ + 1 * TILE_BYTES + off_, Al + ga_);     \
        if (tm & 1) cp_async16(sbase_ + 3 * TILE_BYTES + off_, Bl + gb_);     \
    }                                                                         \
    cp_commit();                                                              \
} while (0)

    const int NT = K / BK;
    LOAD_STAGE(0, 0);

    for (int kt = 0; kt < NT; kt++) {
        if (kt + 1 < NT) {
            LOAD_STAGE((kt + 1) & 1, kt + 1);
            asm volatile("cp.async.wait_group 1;" ::: "memory");
        } else {
            asm volatile("cp.async.wait_group 0;" ::: "memory");
        }
        __syncthreads();

        const uint32_t sbase = su + (uint32_t)(kt & 1) * STAGE_BYTES;
        #pragma unroll
        for (int ks = 0; ks < 2; ks++) {
            uint32_t ah[2][4], al[2][4];
            #pragma unroll
            for (int i = 0; i < 2; i++) {
                const int r   = warp_m * 32 + i * 16 + (lane & 15);
                const int col = ks * 16 + (lane >> 4) * 8;
                const uint32_t ad = sbase + (uint32_t)(r * TSTRIDE + col) * 2;
                ldsm4(ad, ah[i][0], ah[i][1], ah[i][2], ah[i][3]);
                if (tm & 2)
                    ldsm4(ad + TILE_BYTES, al[i][0], al[i][1], al[i][2], al[i][3]);
            }
            const int g  = lane >> 3, i8 = lane & 7;
            const int n0r = warp_n * 64 + ((g >> 1) << 3) + i8;
            const int bcol = ks * 16 + (g & 1) * 8;
            const uint32_t bd0 = sbase + 2 * TILE_BYTES +
                                 (uint32_t)(n0r * TSTRIDE + bcol) * 2;
            // B-hi double-buffered over p
            uint32_t bh0, bh1, bh2, bh3;
            uint32_t bn0_, bn1_, bn2_, bn3_;
            ldsm4(bd0, bh0, bh1, bh2, bh3);
            #pragma unroll
            for (int p = 0; p < 4; p++) {
                const uint32_t bd = bd0 + (uint32_t)(p * 16 * TSTRIDE * 2);
                if (p < 3)
                    ldsm4(bd + (uint32_t)(16 * TSTRIDE * 2), bn0_, bn1_, bn2_, bn3_);
                uint32_t c0, c1, c2, c3;
                if (tm & 1)
                    ldsm4(bd + TILE_BYTES, c0, c1, c2, c3);
                #pragma unroll
                for (int i = 0; i < 2; i++) {
                    hmma(acc[i][2*p],   ah[i], bh0, bh1);
                    hmma(acc[i][2*p+1], ah[i], bh2, bh3);
                }
                if (tm & 2) {
                    #pragma unroll
                    for (int i = 0; i < 2; i++) {
                        hmma(acc[i][2*p],   al[i], bh0, bh1);
                        hmma(acc[i][2*p+1], al[i], bh2, bh3);
                    }
                }
                if (tm & 1) {
                    #pragma unroll
                    for (int i = 0; i < 2; i++) {
                        hmma(acc[i][2*p],   ah[i], c0, c1);
                        hmma(acc[i][2*p+1], ah[i], c2, c3);
                    }
                }
                bh0 = bn0_; bh1 = bn1_; bh2 = bn2_; bh3 = bn3_;
            }
        }
        __syncthreads();
    }
#undef LOAD_STAGE

    // ---- epilogue ----
    const int tq = lane >> 2, tr = lane & 3;
    const float gam = (mode == 3) ? P.gpt[0] : 0.0f;
    #pragma unroll
    for (int i = 0; i < 2; i++) {
        #pragma unroll
        for (int h2 = 0; h2 < 2; h2++) {
            const int row = bm0 + warp_m * 32 + i * 16 + tq + h2 * 8;
            const float bm_ = (mode == 0) ? P.bias[j][row] : 0.0f;
            #pragma unroll
            for (int q = 0; q < 8; q++) {
                const int col = bn0 + warp_n * 64 + q * 8 + tr * 2;
                float v0 = acc[i][q][h2 * 2 + 0];
                float v1 = acc[i][q][h2 * 2 + 1];
                const size_t idx = (size_t)row * N + col;
                if (mode == 0) {
                    v0 += bm_; v1 += bm_;
                    const __half h0 = __float2half_rn(v0);
                    const __half h1 = __float2half_rn(v1);
                    *reinterpret_cast<__half2*>(P.Ch[j] + idx) = __halves2half2(h0, h1);
                    *reinterpret_cast<__half2*>(P.Cl[j] + idx) =
                        __halves2half2(__float2half_rn(v0 - __half2float(h0)),
                                       __float2half_rn(v1 - __half2float(h1)));
                } else if (mode == 1) {
                    v0 += P.bias[j][col]; v1 += P.bias[j][col + 1];
                    *reinterpret_cast<__half2*>(P.Ch[j] + idx) =
                        __halves2half2(__float2half_rn(v0), __float2half_rn(v1));
                } else if (mode == 2) {
                    *reinterpret_cast<float2*>(P.Cf[j] + idx) = make_float2(v0, v1);
                } else {
                    const float2 a2 = *reinterpret_cast<const float2*>(P.xf + idx);
                    const float2 b2 = *reinterpret_cast<const float2*>(P.xl + idx);
                    *reinterpret_cast<float2*>(P.Cf[j] + idx) =
                        make_float2(gam * v0 + 0.5f * (a2.x + b2.x),
                                    gam * v1 + 0.5f * (a2.y + b2.y));
                }
            }
        }
    }
}

// ---------------- batched transpose + fp16 split ----------------------------
struct TJobs { const float* x[3]; __half* th[3]; __half* tl[3]; };
__global__ __launch_bounds__(256)
void transpose_split(TJobs T)
{
    __shared__ float t[32][33];
    const int z = blockIdx.z;
    const float* __restrict__ x = T.x[z];
    __half* __restrict__ th = T.th[z];
    __half* __restrict__ tl = T.tl[z];
    const int tx = threadIdx.x & 31, ty = threadIdx.x >> 5;
    const int c0 = blockIdx.x * 32;
    const int r0 = blockIdx.y * 32;
    #pragma unroll
    for (int i = 0; i < 4; i++)
        t[ty + i * 8][tx] = x[(size_t)(r0 + ty + i * 8) * HW + c0 + tx];
    __syncthreads();
    #pragma unroll
    for (int i = 0; i < 4; i++) {
        const float v = t[tx][ty + i * 8];
        const size_t idx = (size_t)(c0 + ty + i * 8) * C_FULL + r0 + tx;
        const __half h = __float2half_rn(v);
        th[idx] = h;
        tl[idx] = __float2half_rn(v - __half2float(h));
    }
}

// ---------------- merged weight splits (lo optional) ------------------------
struct SJobs { const float* x[4]; __half* h[4]; __half* l[4]; int end[4]; };
__global__ __launch_bounds__(256)
void split4_kernel(SJobs S)
{
    int i = blockIdx.x * 256 + threadIdx.x;
    int j = 0;
    #pragma unroll
    for (int t = 1; t < 4; t++) if (i >= S.end[t - 1]) j = t;
    const int base = (j == 0) ? 0 : S.end[j - 1];
    if (i >= S.end[3]) return;
    const int k = i - base;
    const float v = S.x[j][k];
    const __half hh = __float2half_rn(v);
    S.h[j][k] = hh;
    if (S.l[j]) S.l[j][k] = __float2half_rn(v - __half2float(hh));
}

// ---------------- fused dual softmax over split-K partials ------------------
__global__ __launch_bounds__(256)
void softmax_sum_kernel(const float* __restrict__ LF0, const float* __restrict__ LF1,
                        const float* __restrict__ LL0, const float* __restrict__ LL1,
                        __half* __restrict__ Sh, __half* __restrict__ Sl)
{
    const int row = blockIdx.x;
    const int tid = threadIdx.x;
    __shared__ float red[256];

    const size_t rb = (size_t)row * 1024;
    float vf[4], vl[4];
    #pragma unroll
    for (int k = 0; k < 4; k++) {
        const size_t ix = rb + tid + 256 * k;
        vf[k] = LF0[ix] + LF1[ix];
        vl[k] = LL0[ix] + LL1[ix];
    }

    float m = fmaxf(fmaxf(vf[0], vf[1]), fmaxf(vf[2], vf[3]));
    red[tid] = m; __syncthreads();
    for (int s = 128; s > 0; s >>= 1) { if (tid < s) red[tid] = fmaxf(red[tid], red[tid + s]); __syncthreads(); }
    const float Mf = red[0]; __syncthreads();

    float ef[4], sf = 0.0f;
    #pragma unroll
    for (int k = 0; k < 4; k++) { ef[k] = expf(vf[k] - Mf); sf += ef[k]; }
    red[tid] = sf; __syncthreads();
    for (int s = 128; s > 0; s >>= 1) { if (tid < s) red[tid] += red[tid + s]; __syncthreads(); }
    const float Sf = red[0]; __syncthreads();

    m = fmaxf(fmaxf(vl[0], vl[1]), fmaxf(vl[2], vl[3]));
    red[tid] = m; __syncthreads();
    for (int s = 128; s > 0; s >>= 1) { if (tid < s) red[tid] = fmaxf(red[tid], red[tid + s]); __syncthreads(); }
    const float Ml = red[0]; __syncthreads();

    float el[4], sl = 0.0f;
    #pragma unroll
    for (int k = 0; k < 4; k++) { el[k] = expf(vl[k] - Ml); sl += el[k]; }
    red[tid] = sl; __syncthreads();
    for (int s = 128; s > 0; s >>= 1) { if (tid < s) red[tid] += red[tid + s]; __syncthreads(); }
    const float Sl_ = red[0];

    const float invf = 1.0f / Sf, invl = 1.0f / Sl_;
    #pragma unroll
    for (int k = 0; k < 4; k++) {
        const float v = ef[k] * invf + el[k] * invl;
        const size_t idx = rb + tid + 256 * k;
        const __half h = __float2half_rn(v);
        Sh[idx] = h;
        Sl[idx] = __float2half_rn(v - __half2float(h));
    }
}

// ---------------------------------------------------------------------------
extern "C" void kernel_launch(void* const* d_in, const int* in_sizes, int n_in,
                              void* d_out, int out_size)
{
    (void)in_sizes; (void)n_in; (void)out_size;
    const float* x_f   = (const float*)d_in[0];
    const float* x_m   = (const float*)d_in[1];
    const float* x_l   = (const float*)d_in[2];
    const float* Wq    = (const float*)d_in[3];
    const float* bq    = (const float*)d_in[4];
    const float* Wk1   = (const float*)d_in[5];
    const float* bk1   = (const float*)d_in[6];
    const float* Wk2   = (const float*)d_in[7];
    const float* bk2   = (const float*)d_in[8];
    const float* Wv    = (const float*)d_in[9];
    const float* bv    = (const float*)d_in[10];
    const float* gamma = (const float*)d_in[11];
    float* out = (float*)d_out;

    __half *xTm_h, *xTm_l, *xTf_h, *xTf_l, *xTl_h, *xTl_l;
    __half *wq_h, *wq_l, *wk1_h, *wk1_l, *wk2_h, *wk2_l, *wv_h;
    __half *q_h, *q_l, *kf_h, *kf_l, *kl_h, *kl_l, *vT_h, *s_h, *s_l;
    float *lf0, *lf1, *ll0, *ll1;
    cudaGetSymbolAddress((void**)&xTm_h, g_xTm_h); cudaGetSymbolAddress((void**)&xTm_l, g_xTm_l);
    cudaGetSymbolAddress((void**)&xTf_h, g_xTf_h); cudaGetSymbolAddress((void**)&xTf_l, g_xTf_l);
    cudaGetSymbolAddress((void**)&xTl_h, g_xTl_h); cudaGetSymbolAddress((void**)&xTl_l, g_xTl_l);
    cudaGetSymbolAddress((void**)&wq_h,  g_Wq_h);  cudaGetSymbolAddress((void**)&wq_l,  g_Wq_l);
    cudaGetSymbolAddress((void**)&wk1_h, g_Wk1_h); cudaGetSymbolAddress((void**)&wk1_l, g_Wk1_l);
    cudaGetSymbolAddress((void**)&wk2_h, g_Wk2_h); cudaGetSymbolAddress((void**)&wk2_l, g_Wk2_l);
    cudaGetSymbolAddress((void**)&wv_h,  g_Wv_h);
    cudaGetSymbolAddress((void**)&q_h,  g_q_h);  cudaGetSymbolAddress((void**)&q_l,  g_q_l);
    cudaGetSymbolAddress((void**)&kf_h, g_kf_h); cudaGetSymbolAddress((void**)&kf_l, g_kf_l);
    cudaGetSymbolAddress((void**)&kl_h, g_kl_h); cudaGetSymbolAddress((void**)&kl_l, g_kl_l);
    cudaGetSymbolAddress((void**)&vT_h, g_vT_h);
    cudaGetSymbolAddress((void**)&s_h,  g_S_h);  cudaGetSymbolAddress((void**)&s_l,  g_S_l);
    cudaGetSymbolAddress((void**)&lf0, g_lf0);   cudaGetSymbolAddress((void**)&lf1, g_lf1);
    cudaGetSymbolAddress((void**)&ll0, g_ll0);   cudaGetSymbolAddress((void**)&ll1, g_ll1);

    cudaFuncSetAttribute(mma_gemm, cudaFuncAttributeMaxDynamicSharedMemorySize, GEMM_SMEM);

    // 1) weight splits
    {
        SJobs S = {};
        S.x[0] = Wq;  S.h[0] = wq_h;  S.l[0] = wq_l;
        S.x[1] = Wk1; S.h[1] = wk1_h; S.l[1] = wk1_l;
        S.x[2] = Wk2; S.h[2] = wk2_h; S.l[2] = wk2_l;
        S.x[3] = Wv;  S.h[3] = wv_h;  S.l[3] = nullptr;
        int n0 = C_HALF * C_FULL;
        S.end[0] = n0; S.end[1] = 2 * n0; S.end[2] = 3 * n0;
        S.end[3] = 3 * n0 + C_FULL * C_FULL;
        split4_kernel<<<(S.end[3] + 255) / 256, 256>>>(S);
    }

    // 2) activation transposes + splits
    {
        TJobs T = {};
        T.x[0] = x_m; T.th[0] = xTm_h; T.tl[0] = xTm_l;
        T.x[1] = x_f; T.th[1] = xTf_h; T.tl[1] = xTf_l;
        T.x[2] = x_l; T.th[2] = xTl_h; T.tl[2] = xTl_l;
        transpose_split<<<dim3(HW / 32, C_FULL / 32, 3), 256>>>(T);
    }

    // 3) all 4 conv GEMMs in ONE launch (640 CTAs, 2/SM)
    {
        Jobs P = {};
        const __half* Ahs[3] = {wq_h, wk1_h, wk2_h};
        const __half* Als[3] = {wq_l, wk1_l, wk2_l};
        const __half* Bhs[3] = {xTm_h, xTf_h, xTl_h};
        const __half* Bls[3] = {xTm_l, xTf_l, xTl_l};
        __half* Chs[3] = {q_h, kf_h, kl_h};
        __half* Cls[3] = {q_l, kf_l, kl_l};
        const float* bs[3] = {bq, bk1, bk2};
        for (int t = 0; t < 3; t++) {
            P.Ah[t] = Ahs[t]; P.Al[t] = Als[t]; P.Bh[t] = Bhs[t]; P.Bl[t] = Bls[t];
            P.Ch[t] = Chs[t]; P.Cl[t] = Cls[t]; P.bias[t] = bs[t];
            P.N[t] = HW; P.K[t] = C_FULL; P.Kld[t] = C_FULL; P.koff[t] = 0;
            P.gx[t] = HW / BN;                               // 32
            P.tm[t] = 3; P.mode[t] = 0; P.blk0[t] = t * 128; // 4 y * 32
        }
        P.Ah[3] = xTm_h; P.Al[3] = xTm_l; P.Bh[3] = wv_h; P.Bl[3] = nullptr;
        P.Ch[3] = vT_h; P.bias[3] = bv;
        P.N[3] = C_FULL; P.K[3] = C_FULL; P.Kld[3] = C_FULL; P.koff[3] = 0;
        P.gx[3] = C_FULL / BN;                               // 8
        P.tm[3] = 2; P.mode[3] = 1; P.blk0[3] = 384;         // 32 y * 8 = 256
        P.njobs = 4;
        mma_gemm<<<640, NTHR, GEMM_SMEM>>>(P);
    }

    // 4) logits, split-K=2 (4 jobs x 64 CTAs = 256, 2/SM => 0.86 wave)
    {
        Jobs P = {};
        const __half* As[4] = {kf_h, kf_h, kl_h, kl_h};
        const __half* Als[4] = {kf_l, kf_l, kl_l, kl_l};
        float* Cs[4] = {lf0, lf1, ll0, ll1};
        const int kos[4] = {0, 1024, 0, 1024};
        for (int t = 0; t < 4; t++) {
            P.Ah[t] = As[t]; P.Al[t] = Als[t]; P.Bh[t] = q_h; P.Bl[t] = q_l;
            P.Cf[t] = Cs[t];
            P.N[t] = C_FULL; P.K[t] = 1024; P.Kld[t] = KLOG; P.koff[t] = kos[t];
            P.gx[t] = C_FULL / BN;                           // 8
            P.tm[t] = 3; P.mode[t] = 2; P.blk0[t] = t * 64;  // 8 y * 8
        }
        P.njobs = 4;
        mma_gemm<<<256, NTHR, GEMM_SMEM>>>(P);
    }

    // 5) S = softmax(lf0+lf1) + softmax(ll0+ll1)
    softmax_sum_kernel<<<C_FULL, 256>>>(lf0, lf1, ll0, ll1, s_h, s_l);

    // 6) out = gamma * (S @ vT^T) + 0.5*(x_f + x_l)   (256 CTAs)
    {
        Jobs P = {};
        P.Ah[0] = s_h; P.Al[0] = s_l; P.Bh[0] = vT_h; P.Bl[0] = nullptr;
        P.Cf[0] = out; P.xf = x_f; P.xl = x_l; P.gpt = gamma;
        P.N[0] = HW; P.K[0] = C_FULL; P.Kld[0] = C_FULL; P.koff[0] = 0;
        P.gx[0] = HW / BN;                                   // 32
        P.tm[0] = 2; P.mode[0] = 3; P.blk0[0] = 0;
        P.njobs = 1;
        mma_gemm<<<256, NTHR, GEMM_SMEM>>>(P);
    }
}

// round 10
// speedup vs baseline: 1.0787x; 1.0234x over previous
#include <cuda_runtime.h>
#include <cuda_fp16.h>
#include <math.h>
#include <stdint.h>

#define C_FULL 1024
#define C_HALF 512
#define HW     4096
#define KLOG   2048

// ---------------- scratch (device globals; no runtime allocation) ----------
__device__ __half g_xTm_h[HW*C_FULL], g_xTm_l[HW*C_FULL];
__device__ __half g_xTf_h[HW*C_FULL], g_xTf_l[HW*C_FULL];
__device__ __half g_xTl_h[HW*C_FULL], g_xTl_l[HW*C_FULL];
__device__ __half g_Wq_h [C_HALF*C_FULL], g_Wq_l [C_HALF*C_FULL];
__device__ __half g_Wk1_h[C_HALF*C_FULL], g_Wk1_l[C_HALF*C_FULL];
__device__ __half g_Wk2_h[C_HALF*C_FULL], g_Wk2_l[C_HALF*C_FULL];
__device__ __half g_Wv_h [C_FULL*C_FULL];                 // lo of Wv unused
__device__ __half g_q_h [C_HALF*HW], g_q_l [C_HALF*HW];
__device__ __half g_kf_h[C_HALF*HW], g_kf_l[C_HALF*HW];
__device__ __half g_kl_h[C_HALF*HW], g_kl_l[C_HALF*HW];
__device__ __half g_vT_h[HW*C_FULL];                      // lo of V unused
__device__ float  g_lf0[C_FULL*C_FULL], g_lf1[C_FULL*C_FULL];
__device__ float  g_ll0[C_FULL*C_FULL], g_ll1[C_FULL*C_FULL];
__device__ __half g_S_h[C_FULL*C_FULL];                   // S lo dropped (1-term final)

// ---------------- helpers ---------------------------------------------------
__device__ __forceinline__ uint32_t smem_u32(const void* p) {
    uint32_t r;
    asm("{ .reg .u64 t; cvta.to.shared.u64 t, %1; cvt.u32.u64 %0, t; }"
        : "=r"(r) : "l"(p));
    return r;
}
__device__ __forceinline__ void cp_async16(uint32_t dst, const void* src) {
    asm volatile("cp.async.cg.shared.global [%0], [%1], 16;" :: "r"(dst), "l"(src));
}
__device__ __forceinline__ void cp_commit() { asm volatile("cp.async.commit_group;"); }

__device__ __forceinline__ void ldsm4(uint32_t addr, uint32_t& r0, uint32_t& r1,
                                      uint32_t& r2, uint32_t& r3) {
    asm volatile("ldmatrix.sync.aligned.m8n8.x4.shared.b16 {%0,%1,%2,%3}, [%4];"
                 : "=r"(r0), "=r"(r1), "=r"(r2), "=r"(r3) : "r"(addr));
}
__device__ __forceinline__ void hmma(float* d, const uint32_t* a,
                                     uint32_t b0, uint32_t b1) {
    asm volatile("mma.sync.aligned.m16n8k16.row.col.f32.f16.f16.f32 "
                 "{%0,%1,%2,%3}, {%4,%5,%6,%7}, {%8,%9}, {%0,%1,%2,%3};"
                 : "+f"(d[0]), "+f"(d[1]), "+f"(d[2]), "+f"(d[3])
                 : "r"(a[0]), "r"(a[1]), "r"(a[2]), "r"(a[3]),
                   "r"(b0), "r"(b1));
}

// ---------------- unified multi-job GEMM (templated core) -------------------
// D = A[M,K'] @ B[N,K']^T over K' = [koff, koff+K), fp16-split, fp32 accum.
// tm bit0: add A_h*B_l; tm bit1: add A_l*B_h (A_h*B_h always).
// mode 0: split-store D+bias[m] -> Ch/Cl        (convs q/kf/kl)
// mode 1: hi-store   D+bias[n] -> Ch            (conv vT)
// mode 2: fp32 store D -> Cf                    (logit partials)
// mode 3: fp32 store gamma*D + 0.5*(xf+xl)->Cf  (final)
// BM fixed 128; warp tile 32x64; warp grid 4 x (BN/64).
struct Jobs {
    const __half* Ah[4]; const __half* Al[4];
    const __half* Bh[4]; const __half* Bl[4];
    __half* Ch[4]; __half* Cl[4]; float* Cf[4];
    const float* bias[4];
    const float* xf; const float* xl; const float* gpt;
    int N[4], K[4], Kld[4], koff[4], gx[4], tm[4], mode[4], blk0[4];
    int njobs;
};

template<int BN_, int BK_, int NTHR_, int MINCTA_>
__global__ __launch_bounds__(NTHR_, MINCTA_)
void mma_gemm(Jobs P)
{
    constexpr int TS = BK_ + 8;                    // halves per smem row
    constexpr int TILE_A = 128 * TS * 2;           // bytes
    constexpr int TILE_B = BN_ * TS * 2;
    constexpr int STAGE  = 2 * TILE_A + 2 * TILE_B;
    constexpr int KC     = BK_ / 8;                // 8-half chunks per row
    constexpr int A_IT   = 128 * KC / NTHR_;
    constexpr int B_IT   = BN_ * KC / NTHR_;
    constexpr int KSN    = BK_ / 16;

    extern __shared__ __half sm[];
    int j = 0;
    #pragma unroll
    for (int t = 1; t < 4; t++)
        if (t < P.njobs && (int)blockIdx.x >= P.blk0[t]) j = t;
    const int rel = blockIdx.x - P.blk0[j];
    const int bx = rel % P.gx[j], by = rel / P.gx[j];

    const __half* __restrict__ Ah = P.Ah[j];
    const __half* __restrict__ Al = P.Al[j];
    const __half* __restrict__ Bh = P.Bh[j];
    const __half* __restrict__ Bl = P.Bl[j];
    const int N = P.N[j], K = P.K[j], Kld = P.Kld[j], koff = P.koff[j];
    const int tm = P.tm[j], mode = P.mode[j];

    const int tid  = threadIdx.x;
    const int lane = tid & 31, wid = tid >> 5;
    const int warp_m = wid & 3, warp_n = wid >> 2;       // warp tile 32x64
    const int bm0 = by * 128, bn0 = bx * BN_;
    const uint32_t su = smem_u32(sm);

    float acc[2][8][4];
    #pragma unroll
    for (int i = 0; i < 2; i++)
        #pragma unroll
        for (int q = 0; q < 8; q++)
            #pragma unroll
            for (int k = 0; k < 4; k++) acc[i][q][k] = 0.0f;

#define LOAD_STAGE(s, kt) do {                                                \
    const uint32_t sbase_ = su + (uint32_t)(s) * STAGE;                       \
    const size_t col0_ = (size_t)koff + (size_t)(kt) * BK_;                   \
    _Pragma("unroll")                                                         \
    for (int it_ = 0; it_ < A_IT; it_++) {                                    \
        const int c_ = tid + it_ * NTHR_;                                     \
        const int row_ = c_ / KC;                                             \
        const int kc_ = (c_ % KC) * 8;                                        \
        const uint32_t off_ = (uint32_t)(row_ * TS + kc_) * 2;                \
        const size_t ga_ = (size_t)(bm0 + row_) * Kld + col0_ + kc_;          \
        cp_async16(sbase_ + off_, Ah + ga_);                                  \
        if (tm & 2) cp_async16(sbase_ + TILE_A + off_, Al + ga_);             \
    }                                                                         \
    _Pragma("unroll")                                                         \
    for (int it_ = 0; it_ < B_IT; it_++) {                                    \
        const int c_ = tid + it_ * NTHR_;                                     \
        const int row_ = c_ / KC;                                             \
        const int kc_ = (c_ % KC) * 8;                                        \
        const uint32_t off_ = (uint32_t)(row_ * TS + kc_) * 2;                \
        const size_t gb_ = (size_t)(bn0 + row_) * Kld + col0_ + kc_;          \
        cp_async16(sbase_ + 2 * TILE_A + off_, Bh + gb_);                     \
        if (tm & 1) cp_async16(sbase_ + 2 * TILE_A + TILE_B + off_, Bl + gb_);\
    }                                                                         \
    cp_commit();                                                              \
} while (0)

    const int NT = K / BK_;
    LOAD_STAGE(0, 0);

    for (int kt = 0; kt < NT; kt++) {
        if (kt + 1 < NT) {
            LOAD_STAGE((kt + 1) & 1, kt + 1);
            asm volatile("cp.async.wait_group 1;" ::: "memory");
        } else {
            asm volatile("cp.async.wait_group 0;" ::: "memory");
        }
        __syncthreads();

        const uint32_t sbase = su + (uint32_t)(kt & 1) * STAGE;
        #pragma unroll
        for (int ks = 0; ks < KSN; ks++) {
            uint32_t ah[2][4], al[2][4];
            #pragma unroll
            for (int i = 0; i < 2; i++) {
                const int r   = warp_m * 32 + i * 16 + (lane & 15);
                const int col = ks * 16 + (lane >> 4) * 8;
                const uint32_t ad = sbase + (uint32_t)(r * TS + col) * 2;
                ldsm4(ad, ah[i][0], ah[i][1], ah[i][2], ah[i][3]);
                if (tm & 2)
                    ldsm4(ad + TILE_A, al[i][0], al[i][1], al[i][2], al[i][3]);
            }
            const int g  = lane >> 3, i8 = lane & 7;
            const int n0r = warp_n * 64 + ((g >> 1) << 3) + i8;
            const int bcol = ks * 16 + (g & 1) * 8;
            const uint32_t bd0 = sbase + 2 * TILE_A +
                                 (uint32_t)(n0r * TS + bcol) * 2;
            uint32_t bh0, bh1, bh2, bh3;
            uint32_t bn0_, bn1_, bn2_, bn3_;
            ldsm4(bd0, bh0, bh1, bh2, bh3);
            #pragma unroll
            for (int p = 0; p < 4; p++) {
                const uint32_t bd = bd0 + (uint32_t)(p * 16 * TS * 2);
                if (p < 3)
                    ldsm4(bd + (uint32_t)(16 * TS * 2), bn0_, bn1_, bn2_, bn3_);
                uint32_t c0, c1, c2, c3;
                if (tm & 1)
                    ldsm4(bd + TILE_B, c0, c1, c2, c3);
                #pragma unroll
                for (int i = 0; i < 2; i++) {
                    hmma(acc[i][2*p],   ah[i], bh0, bh1);
                    hmma(acc[i][2*p+1], ah[i], bh2, bh3);
                }
                if (tm & 2) {
                    #pragma unroll
                    for (int i = 0; i < 2; i++) {
                        hmma(acc[i][2*p],   al[i], bh0, bh1);
                        hmma(acc[i][2*p+1], al[i], bh2, bh3);
                    }
                }
                if (tm & 1) {
                    #pragma unroll
                    for (int i = 0; i < 2; i++) {
                        hmma(acc[i][2*p],   ah[i], c0, c1);
                        hmma(acc[i][2*p+1], ah[i], c2, c3);
                    }
                }
                bh0 = bn0_; bh1 = bn1_; bh2 = bn2_; bh3 = bn3_;
            }
        }
        __syncthreads();
    }
#undef LOAD_STAGE

    // ---- epilogue ----
    const int tq = lane >> 2, tr = lane & 3;
    const float gam = (mode == 3) ? P.gpt[0] : 0.0f;
    #pragma unroll
    for (int i = 0; i < 2; i++) {
        #pragma unroll
        for (int h2 = 0; h2 < 2; h2++) {
            const int row = bm0 + warp_m * 32 + i * 16 + tq + h2 * 8;
            const float bm_ = (mode == 0) ? P.bias[j][row] : 0.0f;
            #pragma unroll
            for (int q = 0; q < 8; q++) {
                const int col = bn0 + warp_n * 64 + q * 8 + tr * 2;
                float v0 = acc[i][q][h2 * 2 + 0];
                float v1 = acc[i][q][h2 * 2 + 1];
                const size_t idx = (size_t)row * N + col;
                if (mode == 0) {
                    v0 += bm_; v1 += bm_;
                    const __half h0 = __float2half_rn(v0);
                    const __half h1 = __float2half_rn(v1);
                    *reinterpret_cast<__half2*>(P.Ch[j] + idx) = __halves2half2(h0, h1);
                    *reinterpret_cast<__half2*>(P.Cl[j] + idx) =
                        __halves2half2(__float2half_rn(v0 - __half2float(h0)),
                                       __float2half_rn(v1 - __half2float(h1)));
                } else if (mode == 1) {
                    v0 += P.bias[j][col]; v1 += P.bias[j][col + 1];
                    *reinterpret_cast<__half2*>(P.Ch[j] + idx) =
                        __halves2half2(__float2half_rn(v0), __float2half_rn(v1));
                } else if (mode == 2) {
                    *reinterpret_cast<float2*>(P.Cf[j] + idx) = make_float2(v0, v1);
                } else {
                    const float2 a2 = *reinterpret_cast<const float2*>(P.xf + idx);
                    const float2 b2 = *reinterpret_cast<const float2*>(P.xl + idx);
                    *reinterpret_cast<float2*>(P.Cf[j] + idx) =
                        make_float2(gam * v0 + 0.5f * (a2.x + b2.x),
                                    gam * v1 + 0.5f * (a2.y + b2.y));
                }
            }
        }
    }
}

// Narrow core (convs): 128x128, BK32, 256 thr, 2 CTAs/SM, smem 81920
using GemmN = void(*)(Jobs);
#define SMEM_N (2 * (2 * (128 * 40 * 2) + 2 * (128 * 40 * 2)))   // 81920
// Wide core (logits/final): 128x256, BK64, 512 thr, 1 CTA/SM, smem 221184
#define SMEM_W (2 * (2 * (128 * 72 * 2) + 2 * (256 * 72 * 2)))   // 221184

// ---------------- batched transpose + fp16 split ----------------------------
struct TJobs { const float* x[3]; __half* th[3]; __half* tl[3]; };
__global__ __launch_bounds__(256)
void transpose_split(TJobs T)
{
    __shared__ float t[32][33];
    const int z = blockIdx.z;
    const float* __restrict__ x = T.x[z];
    __half* __restrict__ th = T.th[z];
    __half* __restrict__ tl = T.tl[z];
    const int tx = threadIdx.x & 31, ty = threadIdx.x >> 5;
    const int c0 = blockIdx.x * 32;
    const int r0 = blockIdx.y * 32;
    #pragma unroll
    for (int i = 0; i < 4; i++)
        t[ty + i * 8][tx] = x[(size_t)(r0 + ty + i * 8) * HW + c0 + tx];
    __syncthreads();
    #pragma unroll
    for (int i = 0; i < 4; i++) {
        const float v = t[tx][ty + i * 8];
        const size_t idx = (size_t)(c0 + ty + i * 8) * C_FULL + r0 + tx;
        const __half h = __float2half_rn(v);
        th[idx] = h;
        tl[idx] = __float2half_rn(v - __half2float(h));
    }
}

// ---------------- merged weight splits (lo optional) ------------------------
struct SJobs { const float* x[4]; __half* h[4]; __half* l[4]; int end[4]; };
__global__ __launch_bounds__(256)
void split4_kernel(SJobs S)
{
    int i = blockIdx.x * 256 + threadIdx.x;
    int j = 0;
    #pragma unroll
    for (int t = 1; t < 4; t++) if (i >= S.end[t - 1]) j = t;
    const int base = (j == 0) ? 0 : S.end[j - 1];
    if (i >= S.end[3]) return;
    const int k = i - base;
    const float v = S.x[j][k];
    const __half hh = __float2half_rn(v);
    S.h[j][k] = hh;
    if (S.l[j]) S.l[j][k] = __float2half_rn(v - __half2float(hh));
}

// ---------------- fused dual softmax over split-K partials ------------------
__global__ __launch_bounds__(256)
void softmax_sum_kernel(const float* __restrict__ LF0, const float* __restrict__ LF1,
                        const float* __restrict__ LL0, const float* __restrict__ LL1,
                        __half* __restrict__ Sh)
{
    const int row = blockIdx.x;
    const int tid = threadIdx.x;
    __shared__ float red[256];

    const size_t rb = (size_t)row * 1024;
    float vf[4], vl[4];
    #pragma unroll
    for (int k = 0; k < 4; k++) {
        const size_t ix = rb + tid + 256 * k;
        vf[k] = LF0[ix] + LF1[ix];
        vl[k] = LL0[ix] + LL1[ix];
    }

    float m = fmaxf(fmaxf(vf[0], vf[1]), fmaxf(vf[2], vf[3]));
    red[tid] = m; __syncthreads();
    for (int s = 128; s > 0; s >>= 1) { if (tid < s) red[tid] = fmaxf(red[tid], red[tid + s]); __syncthreads(); }
    const float Mf = red[0]; __syncthreads();

    float ef[4], sf = 0.0f;
    #pragma unroll
    for (int k = 0; k < 4; k++) { ef[k] = expf(vf[k] - Mf); sf += ef[k]; }
    red[tid] = sf; __syncthreads();
    for (int s = 128; s > 0; s >>= 1) { if (tid < s) red[tid] += red[tid + s]; __syncthreads(); }
    const float Sf = red[0]; __syncthreads();

    m = fmaxf(fmaxf(vl[0], vl[1]), fmaxf(vl[2], vl[3]));
    red[tid] = m; __syncthreads();
    for (int s = 128; s > 0; s >>= 1) { if (tid < s) red[tid] = fmaxf(red[tid], red[tid + s]); __syncthreads(); }
    const float Ml = red[0]; __syncthreads();

    float el[4], sl = 0.0f;
    #pragma unroll
    for (int k = 0; k < 4; k++) { el[k] = expf(vl[k] - Ml); sl += el[k]; }
    red[tid] = sl; __syncthreads();
    for (int s = 128; s > 0; s >>= 1) { if (tid < s) red[tid] += red[tid + s]; __syncthreads(); }
    const float Sl_ = red[0];

    const float invf = 1.0f / Sf, invl = 1.0f / Sl_;
    #pragma unroll
    for (int k = 0; k < 4; k++) {
        const float v = ef[k] * invf + el[k] * invl;
        Sh[rb + tid + 256 * k] = __float2half_rn(v);
    }
}

// ---------------------------------------------------------------------------
extern "C" void kernel_launch(void* const* d_in, const int* in_sizes, int n_in,
                              void* d_out, int out_size)
{
    (void)in_sizes; (void)n_in; (void)out_size;
    const float* x_f   = (const float*)d_in[0];
    const float* x_m   = (const float*)d_in[1];
    const float* x_l   = (const float*)d_in[2];
    const float* Wq    = (const float*)d_in[3];
    const float* bq    = (const float*)d_in[4];
    const float* Wk1   = (const float*)d_in[5];
    const float* bk1   = (const float*)d_in[6];
    const float* Wk2   = (const float*)d_in[7];
    const float* bk2   = (const float*)d_in[8];
    const float* Wv    = (const float*)d_in[9];
    const float* bv    = (const float*)d_in[10];
    const float* gamma = (const float*)d_in[11];
    float* out = (float*)d_out;

    __half *xTm_h, *xTm_l, *xTf_h, *xTf_l, *xTl_h, *xTl_l;
    __half *wq_h, *wq_l, *wk1_h, *wk1_l, *wk2_h, *wk2_l, *wv_h;
    __half *q_h, *q_l, *kf_h, *kf_l, *kl_h, *kl_l, *vT_h, *s_h;
    float *lf0, *lf1, *ll0, *ll1;
    cudaGetSymbolAddress((void**)&xTm_h, g_xTm_h); cudaGetSymbolAddress((void**)&xTm_l, g_xTm_l);
    cudaGetSymbolAddress((void**)&xTf_h, g_xTf_h); cudaGetSymbolAddress((void**)&xTf_l, g_xTf_l);
    cudaGetSymbolAddress((void**)&xTl_h, g_xTl_h); cudaGetSymbolAddress((void**)&xTl_l, g_xTl_l);
    cudaGetSymbolAddress((void**)&wq_h,  g_Wq_h);  cudaGetSymbolAddress((void**)&wq_l,  g_Wq_l);
    cudaGetSymbolAddress((void**)&wk1_h, g_Wk1_h); cudaGetSymbolAddress((void**)&wk1_l, g_Wk1_l);
    cudaGetSymbolAddress((void**)&wk2_h, g_Wk2_h); cudaGetSymbolAddress((void**)&wk2_l, g_Wk2_l);
    cudaGetSymbolAddress((void**)&wv_h,  g_Wv_h);
    cudaGetSymbolAddress((void**)&q_h,  g_q_h);  cudaGetSymbolAddress((void**)&q_l,  g_q_l);
    cudaGetSymbolAddress((void**)&kf_h, g_kf_h); cudaGetSymbolAddress((void**)&kf_l, g_kf_l);
    cudaGetSymbolAddress((void**)&kl_h, g_kl_h); cudaGetSymbolAddress((void**)&kl_l, g_kl_l);
    cudaGetSymbolAddress((void**)&vT_h, g_vT_h);
    cudaGetSymbolAddress((void**)&s_h,  g_S_h);
    cudaGetSymbolAddress((void**)&lf0, g_lf0);   cudaGetSymbolAddress((void**)&lf1, g_lf1);
    cudaGetSymbolAddress((void**)&ll0, g_ll0);   cudaGetSymbolAddress((void**)&ll1, g_ll1);

    cudaFuncSetAttribute(mma_gemm<128, 32, 256, 2>,
                         cudaFuncAttributeMaxDynamicSharedMemorySize, SMEM_N);
    cudaFuncSetAttribute(mma_gemm<256, 64, 512, 1>,
                         cudaFuncAttributeMaxDynamicSharedMemorySize, SMEM_W);

    // 1) weight splits
    {
        SJobs S = {};
        S.x[0] = Wq;  S.h[0] = wq_h;  S.l[0] = wq_l;
        S.x[1] = Wk1; S.h[1] = wk1_h; S.l[1] = wk1_l;
        S.x[2] = Wk2; S.h[2] = wk2_h; S.l[2] = wk2_l;
        S.x[3] = Wv;  S.h[3] = wv_h;  S.l[3] = nullptr;
        int n0 = C_HALF * C_FULL;
        S.end[0] = n0; S.end[1] = 2 * n0; S.end[2] = 3 * n0;
        S.end[3] = 3 * n0 + C_FULL * C_FULL;
        split4_kernel<<<(S.end[3] + 255) / 256, 256>>>(S);
    }

    // 2) activation transposes + splits
    {
        TJobs T = {};
        T.x[0] = x_m; T.th[0] = xTm_h; T.tl[0] = xTm_l;
        T.x[1] = x_f; T.th[1] = xTf_h; T.tl[1] = xTf_l;
        T.x[2] = x_l; T.th[2] = xTl_h; T.tl[2] = xTl_l;
        transpose_split<<<dim3(HW / 32, C_FULL / 32, 3), 256>>>(T);
    }

    // 3) all 4 conv GEMMs, narrow core (640 CTAs, 2/SM)
    {
        Jobs P = {};
        const __half* Ahs[3] = {wq_h, wk1_h, wk2_h};
        const __half* Als[3] = {wq_l, wk1_l, wk2_l};
        const __half* Bhs[3] = {xTm_h, xTf_h, xTl_h};
        const __half* Bls[3] = {xTm_l, xTf_l, xTl_l};
        __half* Chs[3] = {q_h, kf_h, kl_h};
        __half* Cls[3] = {q_l, kf_l, kl_l};
        const float* bs[3] = {bq, bk1, bk2};
        for (int t = 0; t < 3; t++) {
            P.Ah[t] = Ahs[t]; P.Al[t] = Als[t]; P.Bh[t] = Bhs[t]; P.Bl[t] = Bls[t];
            P.Ch[t] = Chs[t]; P.Cl[t] = Cls[t]; P.bias[t] = bs[t];
            P.N[t] = HW; P.K[t] = C_FULL; P.Kld[t] = C_FULL; P.koff[t] = 0;
            P.gx[t] = HW / 128;                              // 32
            P.tm[t] = 3; P.mode[t] = 0; P.blk0[t] = t * 128;
        }
        P.Ah[3] = xTm_h; P.Al[3] = xTm_l; P.Bh[3] = wv_h; P.Bl[3] = nullptr;
        P.Ch[3] = vT_h; P.bias[3] = bv;
        P.N[3] = C_FULL; P.K[3] = C_FULL; P.Kld[3] = C_FULL; P.koff[3] = 0;
        P.gx[3] = C_FULL / 128;                              // 8
        P.tm[3] = 2; P.mode[3] = 1; P.blk0[3] = 384;
        P.njobs = 4;
        mma_gemm<128, 32, 256, 2><<<640, 256, SMEM_N>>>(P);
    }

    // 4) logits, wide core, split-K=2 (4 jobs x 32 CTAs = 128)
    {
        Jobs P = {};
        const __half* As[4] = {kf_h, kf_h, kl_h, kl_h};
        const __half* Als[4] = {kf_l, kf_l, kl_l, kl_l};
        float* Cs[4] = {lf0, lf1, ll0, ll1};
        const int kos[4] = {0, 1024, 0, 1024};
        for (int t = 0; t < 4; t++) {
            P.Ah[t] = As[t]; P.Al[t] = Als[t]; P.Bh[t] = q_h; P.Bl[t] = q_l;
            P.Cf[t] = Cs[t];
            P.N[t] = C_FULL; P.K[t] = 1024; P.Kld[t] = KLOG; P.koff[t] = kos[t];
            P.gx[t] = C_FULL / 256;                          // 4
            P.tm[t] = 3; P.mode[t] = 2; P.blk0[t] = t * 32;
        }
        P.njobs = 4;
        mma_gemm<256, 64, 512, 1><<<128, 512, SMEM_W>>>(P);
    }

    // 5) S = softmax(lf0+lf1) + softmax(ll0+ll1)  (hi only)
    softmax_sum_kernel<<<C_FULL, 256>>>(lf0, lf1, ll0, ll1, s_h);

    // 6) out = gamma * (S_h @ vT_h^T) + 0.5*(x_f + x_l)   (1-term, 128 CTAs)
    {
        Jobs P = {};
        P.Ah[0] = s_h; P.Al[0] = nullptr; P.Bh[0] = vT_h; P.Bl[0] = nullptr;
        P.Cf[0] = out; P.xf = x_f; P.xl = x_l; P.gpt = gamma;
        P.N[0] = HW; P.K[0] = C_FULL; P.Kld[0] = C_FULL; P.koff[0] = 0;
        P.gx[0] = HW / 256;                                  // 16
        P.tm[0] = 0; P.mode[0] = 3; P.blk0[0] = 0;
        P.njobs = 1;
        mma_gemm<256, 64, 512, 1><<<128, 512, SMEM_W>>>(P);
    }
}